// round 7
// baseline (speedup 1.0000x reference)
#include <cuda_runtime.h>
#include <cuda_bf16.h>
#include <cstdint>

#define BATCH 4
#define NPTS 8192
#define NSAMP 2048
#define KNN_K 16
#define INDIM 64
#define OUTDIM 128
#define CIN 67

typedef unsigned long long ull;

__device__ int g_knn[BATCH * NSAMP * KNN_K];

// ---------- packed f32x2 helpers (per-lane bit-identical to scalar ops) ----------
__device__ __forceinline__ ull f2pk(float lo, float hi) {
    ull r; asm("mov.b64 %0, {%1,%2};" : "=l"(r) : "f"(lo), "f"(hi)); return r;
}
__device__ __forceinline__ void f2up(ull v, float& lo, float& hi) {
    asm("mov.b64 {%0,%1}, %2;" : "=f"(lo), "=f"(hi) : "l"(v));
}
__device__ __forceinline__ ull f2add(ull a, ull b) {
    ull r; asm("add.rn.f32x2 %0, %1, %2;" : "=l"(r) : "l"(a), "l"(b)); return r;
}
__device__ __forceinline__ ull f2mul(ull a, ull b) {
    ull r; asm("mul.rn.f32x2 %0, %1, %2;" : "=l"(r) : "l"(a), "l"(b)); return r;
}
__device__ __forceinline__ ull f2fma(ull a, ull b, ull c) {
    ull r; asm("fma.rn.f32x2 %0, %1, %2, %3;" : "=l"(r) : "l"(a), "l"(b), "l"(c)); return r;
}

// ============================================================================
// Kernel 1: FPS. One block per batch, 512 threads. Morton counting-sort;
// each thread owns 16 sorted points in registers as 8 f32x2 pairs, split into
// TWO 8-pt sub-buckets with separate bboxes + cached per-half maxima.
// Rescan decision is warp-uniform (__any_sync) -> no divergence machinery;
// updates are idempotent (fminf) so over-execution is safe and exact.
// ============================================================================
#define FPS_T 512
#define FPS_SMEM ((3 * NPTS + NPTS + 1024 + 64 + 112 + 16) * 4)

__device__ __forceinline__ int spread3(int v) {
    return (v & 1) | ((v & 2) << 2) | ((v & 4) << 4);
}

__global__ __launch_bounds__(FPS_T, 1)
void fps_kernel(const float* __restrict__ xyz, float* __restrict__ oxyz) {
    extern __shared__ float sm[];
    float* sxs = sm;
    float* sys = sxs + NPTS;
    float* szs = sys + NPTS;
    int* sorig = (int*)(szs + NPTS);
    int* cellCnt = sorig + NPTS;
    int* cellStart = cellCnt + 512;
    unsigned* pv = (unsigned*)(cellStart + 512);
    unsigned* pp = pv + 32;
    float* wred = (float*)(pp + 32);
    int* gpos0 = (int*)(wred + 102);

    const int b = blockIdx.x;
    const int t = threadIdx.x;
    const int wid = t >> 5;
    const int lane = t & 31;
    const float* bx = xyz + (size_t)b * NPTS * 3;

    // ---- cloud bbox ----
    {
        float lx = 3.4e38f, ly = 3.4e38f, lz = 3.4e38f;
        float hx = -3.4e38f, hy = -3.4e38f, hz = -3.4e38f;
        for (int i = t; i < NPTS; i += FPS_T) {
            float x = bx[3 * i], y = bx[3 * i + 1], z = bx[3 * i + 2];
            lx = fminf(lx, x); hx = fmaxf(hx, x);
            ly = fminf(ly, y); hy = fmaxf(hy, y);
            lz = fminf(lz, z); hz = fmaxf(hz, z);
        }
#pragma unroll
        for (int off = 16; off; off >>= 1) {
            lx = fminf(lx, __shfl_xor_sync(~0u, lx, off));
            ly = fminf(ly, __shfl_xor_sync(~0u, ly, off));
            lz = fminf(lz, __shfl_xor_sync(~0u, lz, off));
            hx = fmaxf(hx, __shfl_xor_sync(~0u, hx, off));
            hy = fmaxf(hy, __shfl_xor_sync(~0u, hy, off));
            hz = fmaxf(hz, __shfl_xor_sync(~0u, hz, off));
        }
        if (lane == 0) {
            wred[wid * 6 + 0] = lx; wred[wid * 6 + 1] = ly; wred[wid * 6 + 2] = lz;
            wred[wid * 6 + 3] = hx; wred[wid * 6 + 4] = hy; wred[wid * 6 + 5] = hz;
        }
        if (t < 512) cellCnt[t] = 0;
    }
    __syncthreads();
    if (t == 0) {
        float lx = wred[0], ly = wred[1], lz = wred[2];
        float hx = wred[3], hy = wred[4], hz = wred[5];
        for (int w = 1; w < 16; w++) {
            lx = fminf(lx, wred[w * 6 + 0]); ly = fminf(ly, wred[w * 6 + 1]);
            lz = fminf(lz, wred[w * 6 + 2]);
            hx = fmaxf(hx, wred[w * 6 + 3]); hy = fmaxf(hy, wred[w * 6 + 4]);
            hz = fmaxf(hz, wred[w * 6 + 5]);
        }
        wred[96] = lx; wred[97] = ly; wred[98] = lz;
        wred[99]  = (hx > lx) ? 7.9999f / (hx - lx) : 0.0f;
        wred[100] = (hy > ly) ? 7.9999f / (hy - ly) : 0.0f;
        wred[101] = (hz > lz) ? 7.9999f / (hz - lz) : 0.0f;
    }
    __syncthreads();
    const float lox = wred[96], loy = wred[97], loz = wred[98];
    const float scx = wred[99], scy = wred[100], scz = wred[101];
    for (int i = t; i < NPTS; i += FPS_T) {
        float x = bx[3 * i], y = bx[3 * i + 1], z = bx[3 * i + 2];
        int qx = (int)((x - lox) * scx); qx = qx < 0 ? 0 : (qx > 7 ? 7 : qx);
        int qy = (int)((y - loy) * scy); qy = qy < 0 ? 0 : (qy > 7 ? 7 : qy);
        int qz = (int)((z - loz) * scz); qz = qz < 0 ? 0 : (qz > 7 ? 7 : qz);
        int ci = (spread3(qx) << 2) | (spread3(qy) << 1) | spread3(qz);
        atomicAdd(&cellCnt[ci], 1);
    }
    __syncthreads();
    if (t < 32) {
        int base = t * 16;
        int loc[16]; int run = 0;
#pragma unroll
        for (int k = 0; k < 16; k++) { loc[k] = run; run += cellCnt[base + k]; }
        int inc = run;
#pragma unroll
        for (int off = 1; off < 32; off <<= 1) {
            int v = __shfl_up_sync(~0u, inc, off);
            if (lane >= off) inc += v;
        }
        int excl = inc - run;
#pragma unroll
        for (int k = 0; k < 16; k++) cellStart[base + k] = excl + loc[k];
    }
    __syncthreads();
    if (t < 512) cellCnt[t] = 0;
    __syncthreads();
    for (int i = t; i < NPTS; i += FPS_T) {
        float x = bx[3 * i], y = bx[3 * i + 1], z = bx[3 * i + 2];
        int qx = (int)((x - lox) * scx); qx = qx < 0 ? 0 : (qx > 7 ? 7 : qx);
        int qy = (int)((y - loy) * scy); qy = qy < 0 ? 0 : (qy > 7 ? 7 : qy);
        int qz = (int)((z - loz) * scz); qz = qz < 0 ? 0 : (qz > 7 ? 7 : qz);
        int ci = (spread3(qx) << 2) | (spread3(qy) << 1) | spread3(qz);
        int p = cellStart[ci] + atomicAdd(&cellCnt[ci], 1);
        sxs[p] = x; sys[p] = y; szs[p] = z;
        sorig[p] = i;
    }
    __syncthreads();

    // ---- load slice: 8 packed pairs; two 8-pt halves with own bboxes ----
    const int base = t * 16;
    ull px2[8], py2[8], pz2[8];
    float pd[16];
    int pay[16];
    float blx[2], bly[2], blz[2], bhx[2], bhy[2], bhz[2];
#pragma unroll
    for (int h = 0; h < 2; h++) {
        blx[h] = 3.4e38f; bly[h] = 3.4e38f; blz[h] = 3.4e38f;
        bhx[h] = -3.4e38f; bhy[h] = -3.4e38f; bhz[h] = -3.4e38f;
    }
#pragma unroll
    for (int m = 0; m < 8; m++) {
        int h = m >> 2;
        int p0 = base + 2 * m, p1 = p0 + 1;
        float x0 = sxs[p0], y0 = sys[p0], z0 = szs[p0];
        float x1 = sxs[p1], y1 = sys[p1], z1 = szs[p1];
        px2[m] = f2pk(x0, x1); py2[m] = f2pk(y0, y1); pz2[m] = f2pk(z0, z1);
        pd[2 * m] = 1e10f; pd[2 * m + 1] = 1e10f;
        int og0 = sorig[p0], og1 = sorig[p1];
        pay[2 * m] = (og0 << 13) | p0;
        pay[2 * m + 1] = (og1 << 13) | p1;
        if (og0 == 0) *gpos0 = p0;
        if (og1 == 0) *gpos0 = p1;
        blx[h] = fminf(blx[h], fminf(x0, x1)); bhx[h] = fmaxf(bhx[h], fmaxf(x0, x1));
        bly[h] = fminf(bly[h], fminf(y0, y1)); bhy[h] = fmaxf(bhy[h], fmaxf(y0, y1));
        blz[h] = fminf(blz[h], fminf(z0, z1)); bhz[h] = fmaxf(bhz[h], fmaxf(z0, z1));
    }
    // initial per-half maxima (all equal -> min payload)
    unsigned hv[2]; int hp[2];
#pragma unroll
    for (int h = 0; h < 2; h++) {
        unsigned v = 0u; int p = 0x7fffffff;
#pragma unroll
        for (int i = 8 * h; i < 8 * h + 8; i++) {
            unsigned vi = __float_as_uint(pd[i]);
            if (vi > v || (vi == v && pay[i] < p)) { v = vi; p = pay[i]; }
        }
        hv[h] = v; hp[h] = p;
    }
    __syncthreads();

    float cx, cy, cz;
    {
        int p0 = *gpos0;
        cx = sxs[p0]; cy = sys[p0]; cz = szs[p0];
        if (t == 0) {
            float* o = oxyz + (size_t)b * NSAMP * 3;
            o[0] = cx; o[1] = cy; o[2] = cz;
        }
    }

    int par = 0;
    for (int s = 1; s < NSAMP; s++) {
        const float mcx = -cx, mcy = -cy, mcz = -cz;
        const ull ncx = f2pk(mcx, mcx);
        const ull ncy = f2pk(mcy, mcy);
        const ull ncz = f2pk(mcz, mcz);
#pragma unroll
        for (int h = 0; h < 2; h++) {
            // bit-exact monotone lower bound vs this half's stale max
            float tx = fmaxf(fmaxf(__fadd_rn(blx[h], mcx), __fadd_rn(cx, -bhx[h])), 0.0f);
            float ty = fmaxf(fmaxf(__fadd_rn(bly[h], mcy), __fadd_rn(cy, -bhy[h])), 0.0f);
            float tz = fmaxf(fmaxf(__fadd_rn(blz[h], mcz), __fadd_rn(cz, -bhz[h])), 0.0f);
            float bnd = __fmul_rn(tx, tx);
            bnd = __fmaf_rn(ty, ty, bnd);
            bnd = __fmaf_rn(tz, tz, bnd);
            bool need = bnd < __uint_as_float(hv[h]);
            if (__any_sync(0xffffffffu, need)) {
                // warp-uniform rescan; fminf updates idempotent for pruned lanes
#pragma unroll
                for (int m = 4 * h; m < 4 * h + 4; m++) {
                    ull dx = f2add(px2[m], ncx);
                    ull dd = f2mul(dx, dx);
                    ull dy = f2add(py2[m], ncy);
                    dd = f2fma(dy, dy, dd);
                    ull dz = f2add(pz2[m], ncz);
                    dd = f2fma(dz, dz, dd);
                    float d0, d1;
                    f2up(dd, d0, d1);
                    pd[2 * m] = fminf(pd[2 * m], d0);
                    pd[2 * m + 1] = fminf(pd[2 * m + 1], d1);
                }
                unsigned v = 0u; int p = 0x7fffffff;
#pragma unroll
                for (int i = 8 * h; i < 8 * h + 8; i++) {
                    unsigned vi = __float_as_uint(pd[i]);
                    if (vi > v || (vi == v && pay[i] < p)) { v = vi; p = pay[i]; }
                }
                hv[h] = v; hp[h] = p;
            }
        }
        // combine halves
        unsigned bmaxv = hv[0]; int bpay = hp[0];
        if (hv[1] > bmaxv || (hv[1] == bmaxv && hp[1] < bpay)) { bmaxv = hv[1]; bpay = hp[1]; }
        // two-level argmax
        unsigned wv = __reduce_max_sync(0xffffffffu, bmaxv);
        unsigned wp = __reduce_min_sync(0xffffffffu,
                                        (bmaxv == wv) ? (unsigned)bpay : 0x7fffffffu);
        if (lane == 0) { pv[par * 16 + wid] = wv; pp[par * 16 + wid] = wp; }
        __syncthreads();
        unsigned v3 = (lane < 16) ? pv[par * 16 + lane] : 0u;
        unsigned p3 = (lane < 16) ? pp[par * 16 + lane] : 0x7fffffffu;
        unsigned gv = __reduce_max_sync(0xffffffffu, v3);
        unsigned gp = __reduce_min_sync(0xffffffffu, (v3 == gv) ? p3 : 0x7fffffffu);
        int pos = (int)(gp & 0x1fffu);
        cx = sxs[pos]; cy = sys[pos]; cz = szs[pos];
        if (t == 0) {
            float* o = oxyz + ((size_t)b * NSAMP + s) * 3;
            o[0] = cx; o[1] = cy; o[2] = cz;
        }
        par ^= 1;
    }
}

// ============================================================================
// Kernel 2: KNN (k=16). Unchanged.
// ============================================================================
#define KTS 1024

__global__ __launch_bounds__(256, 1)
void knn_kernel(const float* __restrict__ xyz, const float* __restrict__ qxyz) {
    __shared__ float stx[KTS], sty[KTS], stz[KTS], st2[KTS];
    __shared__ float smd[64 * 48];
    __shared__ int smi[64 * 48];

    const int t = threadIdx.x;
    const int blk = blockIdx.x;
    const int b = blk >> 5;
    const int q0 = (blk & 31) * 64;
    const int ql = t >> 2;
    const int par = t & 3;
    const int q = q0 + ql;

    const float* qp = qxyz + ((size_t)b * NSAMP + q) * 3;
    const float qx = qp[0], qy = qp[1], qz = qp[2];
    const float q2 = qx * qx + qy * qy + qz * qz;

    float dk[16];
    int ik[16];
#pragma unroll
    for (int i = 0; i < 16; i++) { dk[i] = 3.4e38f; ik[i] = 0; }

    const float* bx = xyz + (size_t)b * NPTS * 3;
    for (int tile = 0; tile < NPTS / KTS; tile++) {
        __syncthreads();
        for (int i = t; i < KTS; i += 256) {
            int p = tile * KTS + i;
            float x = bx[p * 3 + 0], y = bx[p * 3 + 1], z = bx[p * 3 + 2];
            stx[i] = x; sty[i] = y; stz[i] = z;
            st2[i] = x * x + y * y + z * z;
        }
        __syncthreads();
        for (int j = par; j < KTS; j += 4) {
            float dot = qx * stx[j] + qy * sty[j] + qz * stz[j];
            float d = q2 + st2[j] - 2.0f * dot;
            if (d < dk[0]) {
                int idx = tile * KTS + j;
                dk[0] = d; ik[0] = idx;
#pragma unroll
                for (int r = 0; r < 15; r++) {
                    if (dk[r] < dk[r + 1]) {
                        float td = dk[r]; dk[r] = dk[r + 1]; dk[r + 1] = td;
                        int ti = ik[r]; ik[r] = ik[r + 1]; ik[r + 1] = ti;
                    }
                }
            }
        }
    }
    __syncthreads();

    if (par) {
        int basee = ql * 48 + (par - 1) * 16;
#pragma unroll
        for (int i = 0; i < 16; i++) { smd[basee + i] = dk[i]; smi[basee + i] = ik[i]; }
    }
    __syncthreads();

    if (par == 0) {
        for (int e = 0; e < 48; e++) {
            float d = smd[ql * 48 + e];
            int idx = smi[ql * 48 + e];
            if (d < dk[0] || (d == dk[0] && idx < ik[0])) {
                dk[0] = d; ik[0] = idx;
#pragma unroll
                for (int r = 0; r < 15; r++) {
                    bool sw = (dk[r] < dk[r + 1]) ||
                              (dk[r] == dk[r + 1] && ik[r] < ik[r + 1]);
                    if (sw) {
                        float td = dk[r]; dk[r] = dk[r + 1]; dk[r + 1] = td;
                        int ti = ik[r]; ik[r] = ik[r + 1]; ik[r + 1] = ti;
                    }
                }
            }
        }
        int* dst = g_knn + (((size_t)b * NSAMP + q) << 4);
#pragma unroll
        for (int i = 0; i < 16; i++) dst[i] = ik[i];
    }
}

// ============================================================================
// Kernel 3: fused gather + MLP + maxpool + LN (k-loops unrolled 4x).
// ============================================================================
#define MLP_SMEM_FLOATS (8576 + 16384 + 8704 + 16896 + 2048 + 1024)
#define MLP_SMEM (MLP_SMEM_FLOATS * 4)

__global__ __launch_bounds__(256, 1)
void mlp_kernel(const float* __restrict__ xyz, const float* __restrict__ feat,
                const float* __restrict__ newxyz,
                const float* __restrict__ W1, const float* __restrict__ b1,
                const float* __restrict__ W2, const float* __restrict__ b2,
                const float* __restrict__ lg, const float* __restrict__ lb,
                float* __restrict__ outf) {
    extern __shared__ float sm[];
    float* W1s = sm;
    float* W2s = W1s + 8576;
    float* Gs  = W2s + 16384;
    float* Hs  = Gs + 8704;
    float* Ps  = Hs + 16896;
    float* Qs  = Ps + 2048;

    const int t = threadIdx.x;
    const int blk = blockIdx.x;
    const int b = blk >> 8;
    const int q0 = (blk & 255) * 8;

    for (int e = t; e < CIN * OUTDIM; e += 256) {
        int sr = e >> 7, c = e & 127;
        int dr = (sr < 3) ? (64 + sr) : (sr - 3);
        W1s[dr * 128 + c] = W1[e];
    }
    {
        const float4* src = (const float4*)W2;
        float4* dst = (float4*)W2s;
        for (int e = t; e < 4096; e += 256) dst[e] = src[e];
    }
    {
        int r = t >> 1, half = t & 1;
        int qlq = r >> 4, kk = r & 15;
        int q = q0 + qlq;
        int nidx = g_knn[(((size_t)b * NSAMP + q) << 4) + kk];
        const float* frow = feat + ((size_t)b * NPTS + nidx) * INDIM + half * 32;
        float* grow = Gs + r * 68;
#pragma unroll
        for (int i = 0; i < 8; i++) {
            float4 v = *(const float4*)(frow + i * 4);
            *(float4*)(grow + half * 32 + i * 4) = v;
        }
        if (half == 0) {
            const float* prow = xyz + ((size_t)b * NPTS + nidx) * 3;
            const float* crow = newxyz + ((size_t)b * NSAMP + q) * 3;
            grow[64] = prow[0] - crow[0];
            grow[65] = prow[1] - crow[1];
            grow[66] = prow[2] - crow[2];
        }
    }
    __syncthreads();

    const int tx = t & 15, ty = t >> 4;
    const int c0 = tx * 8, r0 = ty * 8;

    float acc[8][8];
    {
        float bb[8];
#pragma unroll
        for (int j = 0; j < 8; j++) bb[j] = __ldg(b1 + c0 + j);
#pragma unroll
        for (int i = 0; i < 8; i++)
#pragma unroll
            for (int j = 0; j < 8; j++) acc[i][j] = bb[j];
    }
#pragma unroll 4
    for (int k = 0; k < CIN; k++) {
        float w[8], g[8];
        float4 w0 = *(const float4*)(W1s + k * 128 + c0);
        float4 w1 = *(const float4*)(W1s + k * 128 + c0 + 4);
        w[0] = w0.x; w[1] = w0.y; w[2] = w0.z; w[3] = w0.w;
        w[4] = w1.x; w[5] = w1.y; w[6] = w1.z; w[7] = w1.w;
#pragma unroll
        for (int i = 0; i < 8; i++) g[i] = Gs[(r0 + i) * 68 + k];
#pragma unroll
        for (int i = 0; i < 8; i++)
#pragma unroll
            for (int j = 0; j < 8; j++) acc[i][j] += g[i] * w[j];
    }
#pragma unroll
    for (int i = 0; i < 8; i++) {
        float4 v0, v1;
        v0.x = fmaxf(acc[i][0], 0.f); v0.y = fmaxf(acc[i][1], 0.f);
        v0.z = fmaxf(acc[i][2], 0.f); v0.w = fmaxf(acc[i][3], 0.f);
        v1.x = fmaxf(acc[i][4], 0.f); v1.y = fmaxf(acc[i][5], 0.f);
        v1.z = fmaxf(acc[i][6], 0.f); v1.w = fmaxf(acc[i][7], 0.f);
        *(float4*)(Hs + (r0 + i) * 132 + c0) = v0;
        *(float4*)(Hs + (r0 + i) * 132 + c0 + 4) = v1;
    }
    __syncthreads();

    {
        float bb[8];
#pragma unroll
        for (int j = 0; j < 8; j++) bb[j] = __ldg(b2 + c0 + j);
#pragma unroll
        for (int i = 0; i < 8; i++)
#pragma unroll
            for (int j = 0; j < 8; j++) acc[i][j] = bb[j];
    }
#pragma unroll 4
    for (int k = 0; k < OUTDIM; k++) {
        float w[8], h[8];
        float4 w0 = *(const float4*)(W2s + k * 128 + c0);
        float4 w1 = *(const float4*)(W2s + k * 128 + c0 + 4);
        w[0] = w0.x; w[1] = w0.y; w[2] = w0.z; w[3] = w0.w;
        w[4] = w1.x; w[5] = w1.y; w[6] = w1.z; w[7] = w1.w;
#pragma unroll
        for (int i = 0; i < 8; i++) h[i] = Hs[(r0 + i) * 132 + k];
#pragma unroll
        for (int i = 0; i < 8; i++)
#pragma unroll
            for (int j = 0; j < 8; j++) acc[i][j] += h[i] * w[j];
    }
    {
        float m[8];
#pragma unroll
        for (int j = 0; j < 8; j++) {
            float v = acc[0][j];
#pragma unroll
            for (int i = 1; i < 8; i++) v = fmaxf(v, acc[i][j]);
            m[j] = v;
        }
        float4 v0, v1;
        v0.x = m[0]; v0.y = m[1]; v0.z = m[2]; v0.w = m[3];
        v1.x = m[4]; v1.y = m[5]; v1.z = m[6]; v1.w = m[7];
        *(float4*)(Ps + ty * 128 + c0) = v0;
        *(float4*)(Ps + ty * 128 + c0 + 4) = v1;
    }
    __syncthreads();
    for (int e = t; e < 1024; e += 256) {
        int q = e >> 7, c = e & 127;
        Qs[e] = fmaxf(Ps[(2 * q) * 128 + c], Ps[(2 * q + 1) * 128 + c]);
    }
    __syncthreads();

    {
        int w = t >> 5, l = t & 31;
        float4 v = *(const float4*)(Qs + w * 128 + l * 4);
        float sum = v.x + v.y + v.z + v.w;
        float sq = fmaf(v.x, v.x, fmaf(v.y, v.y, fmaf(v.z, v.z, v.w * v.w)));
#pragma unroll
        for (int off = 16; off; off >>= 1) {
            sum += __shfl_xor_sync(0xffffffffu, sum, off);
            sq += __shfl_xor_sync(0xffffffffu, sq, off);
        }
        float mu = sum * (1.0f / 128.0f);
        float var = sq * (1.0f / 128.0f) - mu * mu;
        float rs = rsqrtf(var + 1e-5f);
        int qg = q0 + w;
        int c = l * 4;
        float4 o;
        o.x = (v.x - mu) * rs * __ldg(lg + c + 0) + __ldg(lb + c + 0);
        o.y = (v.y - mu) * rs * __ldg(lg + c + 1) + __ldg(lb + c + 1);
        o.z = (v.z - mu) * rs * __ldg(lg + c + 2) + __ldg(lb + c + 2);
        o.w = (v.w - mu) * rs * __ldg(lg + c + 3) + __ldg(lb + c + 3);
        *(float4*)(outf + (((size_t)b * NSAMP + qg) << 7) + c) = o;
    }
}

// ============================================================================
extern "C" void kernel_launch(void* const* d_in, const int* in_sizes, int n_in,
                              void* d_out, int out_size) {
    const float* xyz  = (const float*)d_in[0];
    const float* feat = (const float*)d_in[1];
    const float* W1   = (const float*)d_in[2];
    const float* b1   = (const float*)d_in[3];
    const float* W2   = (const float*)d_in[4];
    const float* b2   = (const float*)d_in[5];
    const float* lg   = (const float*)d_in[6];
    const float* lb   = (const float*)d_in[7];

    float* out = (float*)d_out;
    float* oxyz = out;
    float* ofeat = out + (size_t)BATCH * NSAMP * 3;

    cudaFuncSetAttribute(fps_kernel, cudaFuncAttributeMaxDynamicSharedMemorySize, FPS_SMEM);
    cudaFuncSetAttribute(mlp_kernel, cudaFuncAttributeMaxDynamicSharedMemorySize, MLP_SMEM);

    fps_kernel<<<BATCH, FPS_T, FPS_SMEM>>>(xyz, oxyz);
    knn_kernel<<<128, 256>>>(xyz, oxyz);
    mlp_kernel<<<1024, 256, MLP_SMEM>>>(xyz, feat, oxyz, W1, b1, W2, b2, lg, lb, ofeat);
}

// round 8
// speedup vs baseline: 1.0579x; 1.0579x over previous
#include <cuda_runtime.h>
#include <cuda_bf16.h>
#include <cstdint>

#define BATCH 4
#define NPTS 8192
#define NSAMP 2048
#define KNN_K 16
#define INDIM 64
#define OUTDIM 128
#define CIN 67

typedef unsigned long long ull;

__device__ int g_knn[BATCH * NSAMP * KNN_K];

// ---------- packed f32x2 helpers (per-lane bit-identical to scalar ops) ----------
__device__ __forceinline__ ull f2pk(float lo, float hi) {
    ull r; asm("mov.b64 %0, {%1,%2};" : "=l"(r) : "f"(lo), "f"(hi)); return r;
}
__device__ __forceinline__ void f2up(ull v, float& lo, float& hi) {
    asm("mov.b64 {%0,%1}, %2;" : "=f"(lo), "=f"(hi) : "l"(v));
}
__device__ __forceinline__ ull f2add(ull a, ull b) {
    ull r; asm("add.rn.f32x2 %0, %1, %2;" : "=l"(r) : "l"(a), "l"(b)); return r;
}
__device__ __forceinline__ ull f2mul(ull a, ull b) {
    ull r; asm("mul.rn.f32x2 %0, %1, %2;" : "=l"(r) : "l"(a), "l"(b)); return r;
}
__device__ __forceinline__ ull f2fma(ull a, ull b, ull c) {
    ull r; asm("fma.rn.f32x2 %0, %1, %2, %3;" : "=l"(r) : "l"(a), "l"(b), "l"(c)); return r;
}

// ============================================================================
// Kernel 1: FPS. One block per batch, 1024 threads, 8 points/thread.
// Morton counting-sort; coords in registers as 4 f32x2 pairs; payloads in
// shared (loaded only in rescan tie-break). Warp-uniform rescan decision;
// fminf updates idempotent. Two-level REDUX argmax, 1 barrier/iter.
// ============================================================================
#define FPS_T 1024
#define FPS_SMEM ((3 * NPTS + NPTS + NPTS + 1024 + 128 + 204 + 8) * 4)

__device__ __forceinline__ int spread3(int v) {
    return (v & 1) | ((v & 2) << 2) | ((v & 4) << 4);
}

__global__ __launch_bounds__(FPS_T, 1)
void fps_kernel(const float* __restrict__ xyz, float* __restrict__ oxyz) {
    extern __shared__ float sm[];
    float* sxs = sm;
    float* sys = sxs + NPTS;
    float* szs = sys + NPTS;
    int* sorig = (int*)(szs + NPTS);        // orig index per sorted pos
    int* spay  = sorig + NPTS;              // payload (orig<<13)|pos
    int* cellCnt = spay + NPTS;             // 512
    int* cellStart = cellCnt + 512;         // 512
    unsigned* pv = (unsigned*)(cellStart + 512);  // 2x32
    unsigned* pp = pv + 64;                       // 2x32
    float* wred = (float*)(pp + 64);        // 32 warps x 6 + 6
    int* gpos0 = (int*)(wred + 198);

    const int b = blockIdx.x;
    const int t = threadIdx.x;
    const int wid = t >> 5;
    const int lane = t & 31;
    const float* bx = xyz + (size_t)b * NPTS * 3;

    // ---- cloud bbox ----
    {
        float lx = 3.4e38f, ly = 3.4e38f, lz = 3.4e38f;
        float hx = -3.4e38f, hy = -3.4e38f, hz = -3.4e38f;
        for (int i = t; i < NPTS; i += FPS_T) {
            float x = bx[3 * i], y = bx[3 * i + 1], z = bx[3 * i + 2];
            lx = fminf(lx, x); hx = fmaxf(hx, x);
            ly = fminf(ly, y); hy = fmaxf(hy, y);
            lz = fminf(lz, z); hz = fmaxf(hz, z);
        }
#pragma unroll
        for (int off = 16; off; off >>= 1) {
            lx = fminf(lx, __shfl_xor_sync(~0u, lx, off));
            ly = fminf(ly, __shfl_xor_sync(~0u, ly, off));
            lz = fminf(lz, __shfl_xor_sync(~0u, lz, off));
            hx = fmaxf(hx, __shfl_xor_sync(~0u, hx, off));
            hy = fmaxf(hy, __shfl_xor_sync(~0u, hy, off));
            hz = fmaxf(hz, __shfl_xor_sync(~0u, hz, off));
        }
        if (lane == 0) {
            wred[wid * 6 + 0] = lx; wred[wid * 6 + 1] = ly; wred[wid * 6 + 2] = lz;
            wred[wid * 6 + 3] = hx; wred[wid * 6 + 4] = hy; wred[wid * 6 + 5] = hz;
        }
        if (t < 512) cellCnt[t] = 0;
    }
    __syncthreads();
    if (t == 0) {
        float lx = wred[0], ly = wred[1], lz = wred[2];
        float hx = wred[3], hy = wred[4], hz = wred[5];
        for (int w = 1; w < 32; w++) {
            lx = fminf(lx, wred[w * 6 + 0]); ly = fminf(ly, wred[w * 6 + 1]);
            lz = fminf(lz, wred[w * 6 + 2]);
            hx = fmaxf(hx, wred[w * 6 + 3]); hy = fmaxf(hy, wred[w * 6 + 4]);
            hz = fmaxf(hz, wred[w * 6 + 5]);
        }
        wred[192] = lx; wred[193] = ly; wred[194] = lz;
        wred[195] = (hx > lx) ? 7.9999f / (hx - lx) : 0.0f;
        wred[196] = (hy > ly) ? 7.9999f / (hy - ly) : 0.0f;
        wred[197] = (hz > lz) ? 7.9999f / (hz - lz) : 0.0f;
    }
    __syncthreads();
    const float lox = wred[192], loy = wred[193], loz = wred[194];
    const float scx = wred[195], scy = wred[196], scz = wred[197];
    // ---- histogram ----
    for (int i = t; i < NPTS; i += FPS_T) {
        float x = bx[3 * i], y = bx[3 * i + 1], z = bx[3 * i + 2];
        int qx = (int)((x - lox) * scx); qx = qx < 0 ? 0 : (qx > 7 ? 7 : qx);
        int qy = (int)((y - loy) * scy); qy = qy < 0 ? 0 : (qy > 7 ? 7 : qy);
        int qz = (int)((z - loz) * scz); qz = qz < 0 ? 0 : (qz > 7 ? 7 : qz);
        int ci = (spread3(qx) << 2) | (spread3(qy) << 1) | spread3(qz);
        atomicAdd(&cellCnt[ci], 1);
    }
    __syncthreads();
    // ---- prefix sum (warp 0) ----
    if (t < 32) {
        int base = t * 16;
        int loc[16]; int run = 0;
#pragma unroll
        for (int k = 0; k < 16; k++) { loc[k] = run; run += cellCnt[base + k]; }
        int inc = run;
#pragma unroll
        for (int off = 1; off < 32; off <<= 1) {
            int v = __shfl_up_sync(~0u, inc, off);
            if (lane >= off) inc += v;
        }
        int excl = inc - run;
#pragma unroll
        for (int k = 0; k < 16; k++) cellStart[base + k] = excl + loc[k];
    }
    __syncthreads();
    if (t < 512) cellCnt[t] = 0;
    __syncthreads();
    // ---- scatter ----
    for (int i = t; i < NPTS; i += FPS_T) {
        float x = bx[3 * i], y = bx[3 * i + 1], z = bx[3 * i + 2];
        int qx = (int)((x - lox) * scx); qx = qx < 0 ? 0 : (qx > 7 ? 7 : qx);
        int qy = (int)((y - loy) * scy); qy = qy < 0 ? 0 : (qy > 7 ? 7 : qy);
        int qz = (int)((z - loz) * scz); qz = qz < 0 ? 0 : (qz > 7 ? 7 : qz);
        int ci = (spread3(qx) << 2) | (spread3(qy) << 1) | spread3(qz);
        int p = cellStart[ci] + atomicAdd(&cellCnt[ci], 1);
        sxs[p] = x; sys[p] = y; szs[p] = z;
        sorig[p] = i;
        spay[p] = (i << 13) | p;
        if (i == 0) *gpos0 = p;
    }
    __syncthreads();

    // ---- load this thread's 8-point slice (4 packed pairs) + bbox ----
    const int base = t * 8;
    ull px2[4], py2[4], pz2[4];
    float pd[8];
    float blx = 3.4e38f, bly = 3.4e38f, blz = 3.4e38f;
    float bhx = -3.4e38f, bhy = -3.4e38f, bhz = -3.4e38f;
#pragma unroll
    for (int m = 0; m < 4; m++) {
        int p0 = base + 2 * m, p1 = p0 + 1;
        float x0 = sxs[p0], y0 = sys[p0], z0 = szs[p0];
        float x1 = sxs[p1], y1 = sys[p1], z1 = szs[p1];
        px2[m] = f2pk(x0, x1); py2[m] = f2pk(y0, y1); pz2[m] = f2pk(z0, z1);
        pd[2 * m] = 1e10f; pd[2 * m + 1] = 1e10f;
        blx = fminf(blx, fminf(x0, x1)); bhx = fmaxf(bhx, fmaxf(x0, x1));
        bly = fminf(bly, fminf(y0, y1)); bhy = fmaxf(bhy, fmaxf(y0, y1));
        blz = fminf(blz, fminf(z0, z1)); bhz = fmaxf(bhz, fmaxf(z0, z1));
    }
    // initial cached max: all pd equal -> min payload in slice
    float hvv = 1e10f;
    int hpp;
    {
        int p = 0x7fffffff;
#pragma unroll
        for (int i = 0; i < 8; i++) p = min(p, spay[base + i]);
        hpp = p;
    }
    __syncthreads();

    float cx, cy, cz;
    {
        int p0 = *gpos0;
        cx = sxs[p0]; cy = sys[p0]; cz = szs[p0];
        if (t == 0) {
            float* o = oxyz + (size_t)b * NSAMP * 3;
            o[0] = cx; o[1] = cy; o[2] = cz;
        }
    }

    int par = 0;
    for (int s = 1; s < NSAMP; s++) {
        const float mcx = -cx, mcy = -cy, mcz = -cz;
        // bound test (bit-exact monotone lower bound vs cached stale max)
        float tx = fmaxf(fmaxf(__fadd_rn(blx, mcx), __fadd_rn(cx, -bhx)), 0.0f);
        float ty = fmaxf(fmaxf(__fadd_rn(bly, mcy), __fadd_rn(cy, -bhy)), 0.0f);
        float tz = fmaxf(fmaxf(__fadd_rn(blz, mcz), __fadd_rn(cz, -bhz)), 0.0f);
        float bnd = __fmul_rn(tx, tx);
        bnd = __fmaf_rn(ty, ty, bnd);
        bnd = __fmaf_rn(tz, tz, bnd);
        bool need = bnd < hvv;
        if (__any_sync(0xffffffffu, need)) {
            const ull ncx = f2pk(mcx, mcx);
            const ull ncy = f2pk(mcy, mcy);
            const ull ncz = f2pk(mcz, mcz);
#pragma unroll
            for (int m = 0; m < 4; m++) {
                ull dx = f2add(px2[m], ncx);
                ull dd = f2mul(dx, dx);
                ull dy = f2add(py2[m], ncy);
                dd = f2fma(dy, dy, dd);
                ull dz = f2add(pz2[m], ncz);
                dd = f2fma(dz, dz, dd);
                float d0, d1;
                f2up(dd, d0, d1);
                pd[2 * m] = fminf(pd[2 * m], d0);
                pd[2 * m + 1] = fminf(pd[2 * m + 1], d1);
            }
            // max via tournament, payload via equality select (ties -> min payload)
            float mv = pd[0];
#pragma unroll
            for (int i = 1; i < 8; i++) mv = fmaxf(mv, pd[i]);
            int p = 0x7fffffff;
#pragma unroll
            for (int i = 0; i < 8; i++)
                p = min(p, (pd[i] == mv) ? spay[base + i] : 0x7fffffff);
            hvv = mv; hpp = p;
        }
        // two-level argmax (pd >= 0 so float-bits order == float order)
        unsigned bmaxv = __float_as_uint(hvv);
        unsigned wv = __reduce_max_sync(0xffffffffu, bmaxv);
        unsigned wp = __reduce_min_sync(0xffffffffu,
                                        (bmaxv == wv) ? (unsigned)hpp : 0x7fffffffu);
        if (lane == 0) { pv[par * 32 + wid] = wv; pp[par * 32 + wid] = wp; }
        __syncthreads();
        unsigned v3 = pv[par * 32 + lane];
        unsigned p3 = pp[par * 32 + lane];
        unsigned gv = __reduce_max_sync(0xffffffffu, v3);
        unsigned gp = __reduce_min_sync(0xffffffffu, (v3 == gv) ? p3 : 0x7fffffffu);
        int pos = (int)(gp & 0x1fffu);
        cx = sxs[pos]; cy = sys[pos]; cz = szs[pos];
        if (t == 0) {
            float* o = oxyz + ((size_t)b * NSAMP + s) * 3;
            o[0] = cx; o[1] = cy; o[2] = cz;
        }
        par ^= 1;
    }
}

// ============================================================================
// Kernel 2: KNN (k=16). Unchanged.
// ============================================================================
#define KTS 1024

__global__ __launch_bounds__(256, 1)
void knn_kernel(const float* __restrict__ xyz, const float* __restrict__ qxyz) {
    __shared__ float stx[KTS], sty[KTS], stz[KTS], st2[KTS];
    __shared__ float smd[64 * 48];
    __shared__ int smi[64 * 48];

    const int t = threadIdx.x;
    const int blk = blockIdx.x;
    const int b = blk >> 5;
    const int q0 = (blk & 31) * 64;
    const int ql = t >> 2;
    const int par = t & 3;
    const int q = q0 + ql;

    const float* qp = qxyz + ((size_t)b * NSAMP + q) * 3;
    const float qx = qp[0], qy = qp[1], qz = qp[2];
    const float q2 = qx * qx + qy * qy + qz * qz;

    float dk[16];
    int ik[16];
#pragma unroll
    for (int i = 0; i < 16; i++) { dk[i] = 3.4e38f; ik[i] = 0; }

    const float* bx = xyz + (size_t)b * NPTS * 3;
    for (int tile = 0; tile < NPTS / KTS; tile++) {
        __syncthreads();
        for (int i = t; i < KTS; i += 256) {
            int p = tile * KTS + i;
            float x = bx[p * 3 + 0], y = bx[p * 3 + 1], z = bx[p * 3 + 2];
            stx[i] = x; sty[i] = y; stz[i] = z;
            st2[i] = x * x + y * y + z * z;
        }
        __syncthreads();
        for (int j = par; j < KTS; j += 4) {
            float dot = qx * stx[j] + qy * sty[j] + qz * stz[j];
            float d = q2 + st2[j] - 2.0f * dot;
            if (d < dk[0]) {
                int idx = tile * KTS + j;
                dk[0] = d; ik[0] = idx;
#pragma unroll
                for (int r = 0; r < 15; r++) {
                    if (dk[r] < dk[r + 1]) {
                        float td = dk[r]; dk[r] = dk[r + 1]; dk[r + 1] = td;
                        int ti = ik[r]; ik[r] = ik[r + 1]; ik[r + 1] = ti;
                    }
                }
            }
        }
    }
    __syncthreads();

    if (par) {
        int basee = ql * 48 + (par - 1) * 16;
#pragma unroll
        for (int i = 0; i < 16; i++) { smd[basee + i] = dk[i]; smi[basee + i] = ik[i]; }
    }
    __syncthreads();

    if (par == 0) {
        for (int e = 0; e < 48; e++) {
            float d = smd[ql * 48 + e];
            int idx = smi[ql * 48 + e];
            if (d < dk[0] || (d == dk[0] && idx < ik[0])) {
                dk[0] = d; ik[0] = idx;
#pragma unroll
                for (int r = 0; r < 15; r++) {
                    bool sw = (dk[r] < dk[r + 1]) ||
                              (dk[r] == dk[r + 1] && ik[r] < ik[r + 1]);
                    if (sw) {
                        float td = dk[r]; dk[r] = dk[r + 1]; dk[r + 1] = td;
                        int ti = ik[r]; ik[r] = ik[r + 1]; ik[r + 1] = ti;
                    }
                }
            }
        }
        int* dst = g_knn + (((size_t)b * NSAMP + q) << 4);
#pragma unroll
        for (int i = 0; i < 16; i++) dst[i] = ik[i];
    }
}

// ============================================================================
// Kernel 3: fused gather + MLP + maxpool + LN (R5 best-known form).
// ============================================================================
#define MLP_SMEM_FLOATS (8576 + 16384 + 8704 + 16896 + 2048 + 1024)
#define MLP_SMEM (MLP_SMEM_FLOATS * 4)

__global__ __launch_bounds__(256, 1)
void mlp_kernel(const float* __restrict__ xyz, const float* __restrict__ feat,
                const float* __restrict__ newxyz,
                const float* __restrict__ W1, const float* __restrict__ b1,
                const float* __restrict__ W2, const float* __restrict__ b2,
                const float* __restrict__ lg, const float* __restrict__ lb,
                float* __restrict__ outf) {
    extern __shared__ float sm[];
    float* W1s = sm;
    float* W2s = W1s + 8576;
    float* Gs  = W2s + 16384;
    float* Hs  = Gs + 8704;
    float* Ps  = Hs + 16896;
    float* Qs  = Ps + 2048;

    const int t = threadIdx.x;
    const int blk = blockIdx.x;
    const int b = blk >> 8;
    const int q0 = (blk & 255) * 8;

    for (int e = t; e < CIN * OUTDIM; e += 256) {
        int sr = e >> 7, c = e & 127;
        int dr = (sr < 3) ? (64 + sr) : (sr - 3);
        W1s[dr * 128 + c] = W1[e];
    }
    {
        const float4* src = (const float4*)W2;
        float4* dst = (float4*)W2s;
        for (int e = t; e < 4096; e += 256) dst[e] = src[e];
    }
    {
        int r = t >> 1, half = t & 1;
        int qlq = r >> 4, kk = r & 15;
        int q = q0 + qlq;
        int nidx = g_knn[(((size_t)b * NSAMP + q) << 4) + kk];
        const float* frow = feat + ((size_t)b * NPTS + nidx) * INDIM + half * 32;
        float* grow = Gs + r * 68;
#pragma unroll
        for (int i = 0; i < 8; i++) {
            float4 v = *(const float4*)(frow + i * 4);
            *(float4*)(grow + half * 32 + i * 4) = v;
        }
        if (half == 0) {
            const float* prow = xyz + ((size_t)b * NPTS + nidx) * 3;
            const float* crow = newxyz + ((size_t)b * NSAMP + q) * 3;
            grow[64] = prow[0] - crow[0];
            grow[65] = prow[1] - crow[1];
            grow[66] = prow[2] - crow[2];
        }
    }
    __syncthreads();

    const int tx = t & 15, ty = t >> 4;
    const int c0 = tx * 8, r0 = ty * 8;

    float acc[8][8];
    {
        float bb[8];
#pragma unroll
        for (int j = 0; j < 8; j++) bb[j] = __ldg(b1 + c0 + j);
#pragma unroll
        for (int i = 0; i < 8; i++)
#pragma unroll
            for (int j = 0; j < 8; j++) acc[i][j] = bb[j];
    }
    for (int k = 0; k < CIN; k++) {
        float w[8], g[8];
        float4 w0 = *(const float4*)(W1s + k * 128 + c0);
        float4 w1 = *(const float4*)(W1s + k * 128 + c0 + 4);
        w[0] = w0.x; w[1] = w0.y; w[2] = w0.z; w[3] = w0.w;
        w[4] = w1.x; w[5] = w1.y; w[6] = w1.z; w[7] = w1.w;
#pragma unroll
        for (int i = 0; i < 8; i++) g[i] = Gs[(r0 + i) * 68 + k];
#pragma unroll
        for (int i = 0; i < 8; i++)
#pragma unroll
            for (int j = 0; j < 8; j++) acc[i][j] += g[i] * w[j];
    }
#pragma unroll
    for (int i = 0; i < 8; i++) {
        float4 v0, v1;
        v0.x = fmaxf(acc[i][0], 0.f); v0.y = fmaxf(acc[i][1], 0.f);
        v0.z = fmaxf(acc[i][2], 0.f); v0.w = fmaxf(acc[i][3], 0.f);
        v1.x = fmaxf(acc[i][4], 0.f); v1.y = fmaxf(acc[i][5], 0.f);
        v1.z = fmaxf(acc[i][6], 0.f); v1.w = fmaxf(acc[i][7], 0.f);
        *(float4*)(Hs + (r0 + i) * 132 + c0) = v0;
        *(float4*)(Hs + (r0 + i) * 132 + c0 + 4) = v1;
    }
    __syncthreads();

    {
        float bb[8];
#pragma unroll
        for (int j = 0; j < 8; j++) bb[j] = __ldg(b2 + c0 + j);
#pragma unroll
        for (int i = 0; i < 8; i++)
#pragma unroll
            for (int j = 0; j < 8; j++) acc[i][j] = bb[j];
    }
    for (int k = 0; k < OUTDIM; k++) {
        float w[8], h[8];
        float4 w0 = *(const float4*)(W2s + k * 128 + c0);
        float4 w1 = *(const float4*)(W2s + k * 128 + c0 + 4);
        w[0] = w0.x; w[1] = w0.y; w[2] = w0.z; w[3] = w0.w;
        w[4] = w1.x; w[5] = w1.y; w[6] = w1.z; w[7] = w1.w;
#pragma unroll
        for (int i = 0; i < 8; i++) h[i] = Hs[(r0 + i) * 132 + k];
#pragma unroll
        for (int i = 0; i < 8; i++)
#pragma unroll
            for (int j = 0; j < 8; j++) acc[i][j] += h[i] * w[j];
    }
    {
        float m[8];
#pragma unroll
        for (int j = 0; j < 8; j++) {
            float v = acc[0][j];
#pragma unroll
            for (int i = 1; i < 8; i++) v = fmaxf(v, acc[i][j]);
            m[j] = v;
        }
        float4 v0, v1;
        v0.x = m[0]; v0.y = m[1]; v0.z = m[2]; v0.w = m[3];
        v1.x = m[4]; v1.y = m[5]; v1.z = m[6]; v1.w = m[7];
        *(float4*)(Ps + ty * 128 + c0) = v0;
        *(float4*)(Ps + ty * 128 + c0 + 4) = v1;
    }
    __syncthreads();
    for (int e = t; e < 1024; e += 256) {
        int q = e >> 7, c = e & 127;
        Qs[e] = fmaxf(Ps[(2 * q) * 128 + c], Ps[(2 * q + 1) * 128 + c]);
    }
    __syncthreads();

    {
        int w = t >> 5, l = t & 31;
        float4 v = *(const float4*)(Qs + w * 128 + l * 4);
        float sum = v.x + v.y + v.z + v.w;
        float sq = fmaf(v.x, v.x, fmaf(v.y, v.y, fmaf(v.z, v.z, v.w * v.w)));
#pragma unroll
        for (int off = 16; off; off >>= 1) {
            sum += __shfl_xor_sync(0xffffffffu, sum, off);
            sq += __shfl_xor_sync(0xffffffffu, sq, off);
        }
        float mu = sum * (1.0f / 128.0f);
        float var = sq * (1.0f / 128.0f) - mu * mu;
        float rs = rsqrtf(var + 1e-5f);
        int qg = q0 + w;
        int c = l * 4;
        float4 o;
        o.x = (v.x - mu) * rs * __ldg(lg + c + 0) + __ldg(lb + c + 0);
        o.y = (v.y - mu) * rs * __ldg(lg + c + 1) + __ldg(lb + c + 1);
        o.z = (v.z - mu) * rs * __ldg(lg + c + 2) + __ldg(lb + c + 2);
        o.w = (v.w - mu) * rs * __ldg(lg + c + 3) + __ldg(lb + c + 3);
        *(float4*)(outf + (((size_t)b * NSAMP + qg) << 7) + c) = o;
    }
}

// ============================================================================
extern "C" void kernel_launch(void* const* d_in, const int* in_sizes, int n_in,
                              void* d_out, int out_size) {
    const float* xyz  = (const float*)d_in[0];
    const float* feat = (const float*)d_in[1];
    const float* W1   = (const float*)d_in[2];
    const float* b1   = (const float*)d_in[3];
    const float* W2   = (const float*)d_in[4];
    const float* b2   = (const float*)d_in[5];
    const float* lg   = (const float*)d_in[6];
    const float* lb   = (const float*)d_in[7];

    float* out = (float*)d_out;
    float* oxyz = out;
    float* ofeat = out + (size_t)BATCH * NSAMP * 3;

    cudaFuncSetAttribute(fps_kernel, cudaFuncAttributeMaxDynamicSharedMemorySize, FPS_SMEM);
    cudaFuncSetAttribute(mlp_kernel, cudaFuncAttributeMaxDynamicSharedMemorySize, MLP_SMEM);

    fps_kernel<<<BATCH, FPS_T, FPS_SMEM>>>(xyz, oxyz);
    knn_kernel<<<128, 256>>>(xyz, oxyz);
    mlp_kernel<<<1024, 256, MLP_SMEM>>>(xyz, feat, oxyz, W1, b1, W2, b2, lg, lb, ofeat);
}

// round 9
// speedup vs baseline: 1.1852x; 1.1204x over previous
#include <cuda_runtime.h>
#include <cuda_bf16.h>
#include <cstdint>

#define BATCH 4
#define NPTS 8192
#define NSAMP 2048
#define KNN_K 16
#define INDIM 64
#define OUTDIM 128
#define CIN 67

// ---------------- global coordination state ----------------
__device__ int g_knn[BATCH * NSAMP * KNN_K];
__device__ volatile int g_progress[BATCH];   // FPS samples emitted per batch
__device__ int g_knnCtr;                     // KNN task counter (128 tasks)
__device__ int g_mlpCtr;                     // MLP task counter (1024 tasks)
__device__ volatile int g_knnFlag[128];      // per (chunk,batch) completion

__global__ void init_kernel() {
    g_knnCtr = 0;
    g_mlpCtr = 0;
#pragma unroll
    for (int i = 0; i < BATCH; i++) g_progress[i] = 0;
    for (int i = 0; i < 128; i++) g_knnFlag[i] = 0;
}

// named barriers for 256-thread subgroups inside the 512-thread block
#define BAR_MLP() asm volatile("bar.sync 1, 256;" ::: "memory")
#define BAR_KNN() asm volatile("bar.sync 2, 256;" ::: "memory")

// dynamic smem: max of FPS (33984 floats), KNN (10240), MLP (53632)
#define DYN_FLOATS 53632
#define DYN_BYTES (DYN_FLOATS * 4)

__device__ __forceinline__ int spread3(int v) {
    return (v & 1) | ((v & 2) << 2) | ((v & 4) << 4);
}

// ============================================================================
// FPS (R5 proven body, 512 threads, 16 pts/thread in registers) + progress
// ============================================================================
__device__ void fps_part(float* sm, const float* __restrict__ xyz,
                         float* __restrict__ oxyz, int b, int t) {
    float* sxs = sm;
    float* sys = sxs + NPTS;
    float* szs = sys + NPTS;
    int* sorig = (int*)(szs + NPTS);
    int* cellCnt = sorig + NPTS;            // 512
    int* cellStart = cellCnt + 512;         // 512
    unsigned* pv = (unsigned*)(cellStart + 512);  // 2x16
    unsigned* pp = pv + 32;                       // 2x16
    float* wred = (float*)(pp + 32);        // 16x6 + 6
    int* gpos0 = (int*)(wred + 102);

    const int wid = t >> 5;
    const int lane = t & 31;
    const float* bx = xyz + (size_t)b * NPTS * 3;

    // ---- cloud bbox ----
    {
        float lx = 3.4e38f, ly = 3.4e38f, lz = 3.4e38f;
        float hx = -3.4e38f, hy = -3.4e38f, hz = -3.4e38f;
        for (int i = t; i < NPTS; i += 512) {
            float x = bx[3 * i], y = bx[3 * i + 1], z = bx[3 * i + 2];
            lx = fminf(lx, x); hx = fmaxf(hx, x);
            ly = fminf(ly, y); hy = fmaxf(hy, y);
            lz = fminf(lz, z); hz = fmaxf(hz, z);
        }
#pragma unroll
        for (int off = 16; off; off >>= 1) {
            lx = fminf(lx, __shfl_xor_sync(~0u, lx, off));
            ly = fminf(ly, __shfl_xor_sync(~0u, ly, off));
            lz = fminf(lz, __shfl_xor_sync(~0u, lz, off));
            hx = fmaxf(hx, __shfl_xor_sync(~0u, hx, off));
            hy = fmaxf(hy, __shfl_xor_sync(~0u, hy, off));
            hz = fmaxf(hz, __shfl_xor_sync(~0u, hz, off));
        }
        if (lane == 0) {
            wred[wid * 6 + 0] = lx; wred[wid * 6 + 1] = ly; wred[wid * 6 + 2] = lz;
            wred[wid * 6 + 3] = hx; wred[wid * 6 + 4] = hy; wred[wid * 6 + 5] = hz;
        }
        cellCnt[t] = 0;
    }
    __syncthreads();
    if (t == 0) {
        float lx = wred[0], ly = wred[1], lz = wred[2];
        float hx = wred[3], hy = wred[4], hz = wred[5];
        for (int w = 1; w < 16; w++) {
            lx = fminf(lx, wred[w * 6 + 0]); ly = fminf(ly, wred[w * 6 + 1]);
            lz = fminf(lz, wred[w * 6 + 2]);
            hx = fmaxf(hx, wred[w * 6 + 3]); hy = fmaxf(hy, wred[w * 6 + 4]);
            hz = fmaxf(hz, wred[w * 6 + 5]);
        }
        wred[96] = lx; wred[97] = ly; wred[98] = lz;
        wred[99]  = (hx > lx) ? 7.9999f / (hx - lx) : 0.0f;
        wred[100] = (hy > ly) ? 7.9999f / (hy - ly) : 0.0f;
        wred[101] = (hz > lz) ? 7.9999f / (hz - lz) : 0.0f;
    }
    __syncthreads();
    const float lox = wred[96], loy = wred[97], loz = wred[98];
    const float scx = wred[99], scy = wred[100], scz = wred[101];
    for (int i = t; i < NPTS; i += 512) {
        float x = bx[3 * i], y = bx[3 * i + 1], z = bx[3 * i + 2];
        int qx = (int)((x - lox) * scx); qx = qx < 0 ? 0 : (qx > 7 ? 7 : qx);
        int qy = (int)((y - loy) * scy); qy = qy < 0 ? 0 : (qy > 7 ? 7 : qy);
        int qz = (int)((z - loz) * scz); qz = qz < 0 ? 0 : (qz > 7 ? 7 : qz);
        int ci = (spread3(qx) << 2) | (spread3(qy) << 1) | spread3(qz);
        atomicAdd(&cellCnt[ci], 1);
    }
    __syncthreads();
    if (t < 32) {
        int base = t * 16;
        int loc[16]; int run = 0;
#pragma unroll
        for (int k = 0; k < 16; k++) { loc[k] = run; run += cellCnt[base + k]; }
        int inc = run;
#pragma unroll
        for (int off = 1; off < 32; off <<= 1) {
            int v = __shfl_up_sync(~0u, inc, off);
            if (lane >= off) inc += v;
        }
        int excl = inc - run;
#pragma unroll
        for (int k = 0; k < 16; k++) cellStart[base + k] = excl + loc[k];
    }
    __syncthreads();
    cellCnt[t] = 0;
    __syncthreads();
    for (int i = t; i < NPTS; i += 512) {
        float x = bx[3 * i], y = bx[3 * i + 1], z = bx[3 * i + 2];
        int qx = (int)((x - lox) * scx); qx = qx < 0 ? 0 : (qx > 7 ? 7 : qx);
        int qy = (int)((y - loy) * scy); qy = qy < 0 ? 0 : (qy > 7 ? 7 : qy);
        int qz = (int)((z - loz) * scz); qz = qz < 0 ? 0 : (qz > 7 ? 7 : qz);
        int ci = (spread3(qx) << 2) | (spread3(qy) << 1) | spread3(qz);
        int p = cellStart[ci] + atomicAdd(&cellCnt[ci], 1);
        sxs[p] = x; sys[p] = y; szs[p] = z;
        sorig[p] = i;
    }
    __syncthreads();

    const int base = t * 16;
    float px[16], py[16], pz[16], pd[16];
    int pay[16];
    float blx = 3.4e38f, bly = 3.4e38f, blz = 3.4e38f;
    float bhx = -3.4e38f, bhy = -3.4e38f, bhz = -3.4e38f;
#pragma unroll
    for (int i = 0; i < 16; i++) {
        int pos = base + i;
        float x = sxs[pos], y = sys[pos], z = szs[pos];
        px[i] = x; py[i] = y; pz[i] = z;
        pd[i] = 1e10f;
        int og = sorig[pos];
        pay[i] = (og << 13) | pos;
        if (og == 0) *gpos0 = pos;
        blx = fminf(blx, x); bhx = fmaxf(bhx, x);
        bly = fminf(bly, y); bhy = fmaxf(bhy, y);
        blz = fminf(blz, z); bhz = fmaxf(bhz, z);
    }
    unsigned bmaxv; int bpay;
    {
        unsigned bv = 0u; int bp = 0x7fffffff;
#pragma unroll
        for (int i = 0; i < 16; i++) {
            unsigned v = __float_as_uint(pd[i]);
            if (v > bv || (v == bv && pay[i] < bp)) { bv = v; bp = pay[i]; }
        }
        bmaxv = bv; bpay = bp;
    }
    __syncthreads();

    float cx, cy, cz;
    {
        int p0 = *gpos0;
        cx = sxs[p0]; cy = sys[p0]; cz = szs[p0];
        if (t == 0) {
            float* o = oxyz + (size_t)b * NSAMP * 3;
            o[0] = cx; o[1] = cy; o[2] = cz;
        }
    }

    int par = 0;
    for (int s = 1; s < NSAMP; s++) {
        const float mcx = -cx, mcy = -cy, mcz = -cz;
        float tx = fmaxf(fmaxf(__fadd_rn(blx, mcx), __fadd_rn(cx, -bhx)), 0.0f);
        float ty = fmaxf(fmaxf(__fadd_rn(bly, mcy), __fadd_rn(cy, -bhy)), 0.0f);
        float tz = fmaxf(fmaxf(__fadd_rn(blz, mcz), __fadd_rn(cz, -bhz)), 0.0f);
        float bnd = __fmul_rn(tx, tx);
        bnd = __fmaf_rn(ty, ty, bnd);
        bnd = __fmaf_rn(tz, tz, bnd);
        if (bnd < __uint_as_float(bmaxv)) {
#pragma unroll
            for (int i = 0; i < 16; i++) {
                float dx = __fadd_rn(px[i], mcx);
                float dd = __fmul_rn(dx, dx);
                float dy = __fadd_rn(py[i], mcy);
                dd = __fmaf_rn(dy, dy, dd);
                float dz = __fadd_rn(pz[i], mcz);
                dd = __fmaf_rn(dz, dz, dd);
                pd[i] = fminf(pd[i], dd);
            }
            unsigned bv = 0u; int bp = 0x7fffffff;
#pragma unroll
            for (int i = 0; i < 16; i++) {
                unsigned v = __float_as_uint(pd[i]);
                if (v > bv || (v == bv && pay[i] < bp)) { bv = v; bp = pay[i]; }
            }
            bmaxv = bv; bpay = bp;
        }
        unsigned wv = __reduce_max_sync(0xffffffffu, bmaxv);
        unsigned wp = __reduce_min_sync(0xffffffffu,
                                        (bmaxv == wv) ? (unsigned)bpay : 0x7fffffffu);
        if (lane == 0) { pv[par * 16 + wid] = wv; pp[par * 16 + wid] = wp; }
        __syncthreads();
        unsigned v3 = (lane < 16) ? pv[par * 16 + lane] : 0u;
        unsigned p3 = (lane < 16) ? pp[par * 16 + lane] : 0x7fffffffu;
        unsigned gv = __reduce_max_sync(0xffffffffu, v3);
        unsigned gp = __reduce_min_sync(0xffffffffu, (v3 == gv) ? p3 : 0x7fffffffu);
        int pos = (int)(gp & 0x1fffu);
        cx = sxs[pos]; cy = sys[pos]; cz = szs[pos];
        if (t == 0) {
            float* o = oxyz + ((size_t)b * NSAMP + s) * 3;
            o[0] = cx; o[1] = cy; o[2] = cz;
            if ((s & 63) == 63) {
                __threadfence();
                g_progress[b] = s + 1;
            }
        }
        par ^= 1;
    }
    if (t == 0) { __threadfence(); g_progress[b] = NSAMP; }
}

// ============================================================================
// KNN chunk: 64 queries, 256 active threads (4 per query). Named barrier 2.
// ============================================================================
#define KTS 1024

__device__ void knn_chunk(float* sm, const float* __restrict__ xyz,
                          const float* __restrict__ qxyz, int b, int q0, int t) {
    if (t >= 256) return;
    float* stx = sm;
    float* sty = sm + 1024;
    float* stz = sm + 2048;
    float* st2 = sm + 3072;
    float* smd = sm + 4096;               // 64*48
    int*   smi = (int*)(sm + 7168);       // 64*48

    const int ql = t >> 2;
    const int par = t & 3;
    const int q = q0 + ql;

    const float* qp = qxyz + ((size_t)b * NSAMP + q) * 3;
    const float qx = qp[0], qy = qp[1], qz = qp[2];
    const float q2 = qx * qx + qy * qy + qz * qz;

    float dk[16];
    int ik[16];
#pragma unroll
    for (int i = 0; i < 16; i++) { dk[i] = 3.4e38f; ik[i] = 0; }

    const float* bx = xyz + (size_t)b * NPTS * 3;
    for (int tile = 0; tile < NPTS / KTS; tile++) {
        BAR_KNN();
        for (int i = t; i < KTS; i += 256) {
            int p = tile * KTS + i;
            float x = bx[p * 3 + 0], y = bx[p * 3 + 1], z = bx[p * 3 + 2];
            stx[i] = x; sty[i] = y; stz[i] = z;
            st2[i] = x * x + y * y + z * z;
        }
        BAR_KNN();
        for (int j = par; j < KTS; j += 4) {
            float dot = qx * stx[j] + qy * sty[j] + qz * stz[j];
            float d = q2 + st2[j] - 2.0f * dot;
            if (d < dk[0]) {
                int idx = tile * KTS + j;
                dk[0] = d; ik[0] = idx;
#pragma unroll
                for (int r = 0; r < 15; r++) {
                    if (dk[r] < dk[r + 1]) {
                        float td = dk[r]; dk[r] = dk[r + 1]; dk[r + 1] = td;
                        int ti = ik[r]; ik[r] = ik[r + 1]; ik[r + 1] = ti;
                    }
                }
            }
        }
    }
    BAR_KNN();

    if (par) {
        int basee = ql * 48 + (par - 1) * 16;
#pragma unroll
        for (int i = 0; i < 16; i++) { smd[basee + i] = dk[i]; smi[basee + i] = ik[i]; }
    }
    BAR_KNN();

    if (par == 0) {
        for (int e = 0; e < 48; e++) {
            float d = smd[ql * 48 + e];
            int idx = smi[ql * 48 + e];
            if (d < dk[0] || (d == dk[0] && idx < ik[0])) {
                dk[0] = d; ik[0] = idx;
#pragma unroll
                for (int r = 0; r < 15; r++) {
                    bool sw = (dk[r] < dk[r + 1]) ||
                              (dk[r] == dk[r + 1] && ik[r] < ik[r + 1]);
                    if (sw) {
                        float td = dk[r]; dk[r] = dk[r + 1]; dk[r + 1] = td;
                        int ti = ik[r]; ik[r] = ik[r + 1]; ik[r + 1] = ti;
                    }
                }
            }
        }
        int* dst = g_knn + (((size_t)b * NSAMP + q) << 4);
#pragma unroll
        for (int i = 0; i < 16; i++) dst[i] = ik[i];
    }
    BAR_KNN();
}

// ============================================================================
// MLP tile: 8 queries, 256 active threads. Named barrier 1.
// ============================================================================
__device__ void mlp_tile(float* sm, const float* __restrict__ xyz,
                         const float* __restrict__ feat,
                         const float* __restrict__ newxyz,
                         const float* __restrict__ W1, const float* __restrict__ b1,
                         const float* __restrict__ W2, const float* __restrict__ b2,
                         const float* __restrict__ lg, const float* __restrict__ lb,
                         float* __restrict__ outf, int b, int q0, int t) {
    if (t >= 256) return;
    float* W1s = sm;
    float* W2s = W1s + 8576;
    float* Gs  = W2s + 16384;
    float* Hs  = Gs + 8704;
    float* Ps  = Hs + 16896;
    float* Qs  = Ps + 2048;

    for (int e = t; e < CIN * OUTDIM; e += 256) {
        int sr = e >> 7, c = e & 127;
        int dr = (sr < 3) ? (64 + sr) : (sr - 3);
        W1s[dr * 128 + c] = W1[e];
    }
    {
        const float4* src = (const float4*)W2;
        float4* dst = (float4*)W2s;
        for (int e = t; e < 4096; e += 256) dst[e] = src[e];
    }
    {
        int r = t >> 1, half = t & 1;
        int qlq = r >> 4, kk = r & 15;
        int q = q0 + qlq;
        int nidx = g_knn[(((size_t)b * NSAMP + q) << 4) + kk];
        const float* frow = feat + ((size_t)b * NPTS + nidx) * INDIM + half * 32;
        float* grow = Gs + r * 68;
#pragma unroll
        for (int i = 0; i < 8; i++) {
            float4 v = *(const float4*)(frow + i * 4);
            *(float4*)(grow + half * 32 + i * 4) = v;
        }
        if (half == 0) {
            const float* prow = xyz + ((size_t)b * NPTS + nidx) * 3;
            const float* crow = newxyz + ((size_t)b * NSAMP + q) * 3;
            grow[64] = prow[0] - crow[0];
            grow[65] = prow[1] - crow[1];
            grow[66] = prow[2] - crow[2];
        }
    }
    BAR_MLP();

    const int tx = t & 15, ty = t >> 4;
    const int c0 = tx * 8, r0 = ty * 8;

    float acc[8][8];
    {
        float bb[8];
#pragma unroll
        for (int j = 0; j < 8; j++) bb[j] = __ldg(b1 + c0 + j);
#pragma unroll
        for (int i = 0; i < 8; i++)
#pragma unroll
            for (int j = 0; j < 8; j++) acc[i][j] = bb[j];
    }
    for (int k = 0; k < CIN; k++) {
        float w[8], g[8];
        float4 w0 = *(const float4*)(W1s + k * 128 + c0);
        float4 w1 = *(const float4*)(W1s + k * 128 + c0 + 4);
        w[0] = w0.x; w[1] = w0.y; w[2] = w0.z; w[3] = w0.w;
        w[4] = w1.x; w[5] = w1.y; w[6] = w1.z; w[7] = w1.w;
#pragma unroll
        for (int i = 0; i < 8; i++) g[i] = Gs[(r0 + i) * 68 + k];
#pragma unroll
        for (int i = 0; i < 8; i++)
#pragma unroll
            for (int j = 0; j < 8; j++) acc[i][j] += g[i] * w[j];
    }
#pragma unroll
    for (int i = 0; i < 8; i++) {
        float4 v0, v1;
        v0.x = fmaxf(acc[i][0], 0.f); v0.y = fmaxf(acc[i][1], 0.f);
        v0.z = fmaxf(acc[i][2], 0.f); v0.w = fmaxf(acc[i][3], 0.f);
        v1.x = fmaxf(acc[i][4], 0.f); v1.y = fmaxf(acc[i][5], 0.f);
        v1.z = fmaxf(acc[i][6], 0.f); v1.w = fmaxf(acc[i][7], 0.f);
        *(float4*)(Hs + (r0 + i) * 132 + c0) = v0;
        *(float4*)(Hs + (r0 + i) * 132 + c0 + 4) = v1;
    }
    BAR_MLP();

    {
        float bb[8];
#pragma unroll
        for (int j = 0; j < 8; j++) bb[j] = __ldg(b2 + c0 + j);
#pragma unroll
        for (int i = 0; i < 8; i++)
#pragma unroll
            for (int j = 0; j < 8; j++) acc[i][j] = bb[j];
    }
    for (int k = 0; k < OUTDIM; k++) {
        float w[8], h[8];
        float4 w0 = *(const float4*)(W2s + k * 128 + c0);
        float4 w1 = *(const float4*)(W2s + k * 128 + c0 + 4);
        w[0] = w0.x; w[1] = w0.y; w[2] = w0.z; w[3] = w0.w;
        w[4] = w1.x; w[5] = w1.y; w[6] = w1.z; w[7] = w1.w;
#pragma unroll
        for (int i = 0; i < 8; i++) h[i] = Hs[(r0 + i) * 132 + k];
#pragma unroll
        for (int i = 0; i < 8; i++)
#pragma unroll
            for (int j = 0; j < 8; j++) acc[i][j] += h[i] * w[j];
    }
    {
        float m[8];
#pragma unroll
        for (int j = 0; j < 8; j++) {
            float v = acc[0][j];
#pragma unroll
            for (int i = 1; i < 8; i++) v = fmaxf(v, acc[i][j]);
            m[j] = v;
        }
        float4 v0, v1;
        v0.x = m[0]; v0.y = m[1]; v0.z = m[2]; v0.w = m[3];
        v1.x = m[4]; v1.y = m[5]; v1.z = m[6]; v1.w = m[7];
        *(float4*)(Ps + ty * 128 + c0) = v0;
        *(float4*)(Ps + ty * 128 + c0 + 4) = v1;
    }
    BAR_MLP();
    for (int e = t; e < 1024; e += 256) {
        int q = e >> 7, c = e & 127;
        Qs[e] = fmaxf(Ps[(2 * q) * 128 + c], Ps[(2 * q + 1) * 128 + c]);
    }
    BAR_MLP();

    {
        int w = t >> 5, l = t & 31;
        float4 v = *(const float4*)(Qs + w * 128 + l * 4);
        float sum = v.x + v.y + v.z + v.w;
        float sq = fmaf(v.x, v.x, fmaf(v.y, v.y, fmaf(v.z, v.z, v.w * v.w)));
#pragma unroll
        for (int off = 16; off; off >>= 1) {
            sum += __shfl_xor_sync(0xffffffffu, sum, off);
            sq += __shfl_xor_sync(0xffffffffu, sq, off);
        }
        float mu = sum * (1.0f / 128.0f);
        float var = sq * (1.0f / 128.0f) - mu * mu;
        float rs = rsqrtf(var + 1e-5f);
        int qg = q0 + w;
        int c = l * 4;
        float4 o;
        o.x = (v.x - mu) * rs * __ldg(lg + c + 0) + __ldg(lb + c + 0);
        o.y = (v.y - mu) * rs * __ldg(lg + c + 1) + __ldg(lb + c + 1);
        o.z = (v.z - mu) * rs * __ldg(lg + c + 2) + __ldg(lb + c + 2);
        o.w = (v.w - mu) * rs * __ldg(lg + c + 3) + __ldg(lb + c + 3);
        *(float4*)(outf + (((size_t)b * NSAMP + qg) << 7) + c) = o;
    }
    BAR_MLP();
}

// ============================================================================
// Fused persistent kernel: grid 148 (one block per SM, all co-resident).
// Blocks 0-3 run FPS, then all blocks drain KNN task pool, then MLP pool.
// ============================================================================
__global__ __launch_bounds__(512, 1)
void fused_kernel(const float* __restrict__ xyz, const float* __restrict__ feat,
                  const float* __restrict__ W1, const float* __restrict__ b1,
                  const float* __restrict__ W2, const float* __restrict__ b2,
                  const float* __restrict__ lg, const float* __restrict__ lb,
                  float* __restrict__ oxyz, float* __restrict__ ofeat) {
    extern __shared__ float sm[];
    __shared__ int shT;
    const int t = threadIdx.x;
    const int bid = blockIdx.x;

    if (bid < BATCH) {
        fps_part(sm, xyz, oxyz, bid, t);
    }

    // ---- KNN task pool: 128 tasks = (chunk 0..31) x (batch 0..3) ----
    while (true) {
        __syncthreads();
        if (t == 0) shT = atomicAdd(&g_knnCtr, 1);
        __syncthreads();
        int task = shT;
        if (task >= 128) break;
        int chunk = task >> 2;
        int b = task & 3;
        if (t == 0) {
            int need = (chunk + 1) * 64;
            while (g_progress[b] < need) __nanosleep(128);
        }
        __syncthreads();
        knn_chunk(sm, xyz, oxyz, b, chunk * 64, t);
        __syncthreads();
        if (t == 0) { __threadfence(); g_knnFlag[task] = 1; }
    }

    // ---- MLP task pool: 1024 tasks = (qchunk 0..255) x (batch 0..3) ----
    while (true) {
        __syncthreads();
        if (t == 0) shT = atomicAdd(&g_mlpCtr, 1);
        __syncthreads();
        int task = shT;
        if (task >= 1024) break;
        int qc = task >> 2;
        int b = task & 3;
        int flagIdx = ((qc >> 3) << 2) | b;  // containing knn chunk * 4 + b
        if (t == 0) {
            while (g_knnFlag[flagIdx] == 0) __nanosleep(128);
        }
        __syncthreads();
        mlp_tile(sm, xyz, feat, oxyz, W1, b1, W2, b2, lg, lb, ofeat, b, qc * 8, t);
    }
}

// ============================================================================
extern "C" void kernel_launch(void* const* d_in, const int* in_sizes, int n_in,
                              void* d_out, int out_size) {
    const float* xyz  = (const float*)d_in[0];
    const float* feat = (const float*)d_in[1];
    const float* W1   = (const float*)d_in[2];
    const float* b1   = (const float*)d_in[3];
    const float* W2   = (const float*)d_in[4];
    const float* b2   = (const float*)d_in[5];
    const float* lg   = (const float*)d_in[6];
    const float* lb   = (const float*)d_in[7];

    float* out = (float*)d_out;
    float* oxyz = out;                                  // (B, S, 3)
    float* ofeat = out + (size_t)BATCH * NSAMP * 3;     // (B, S, 128)

    cudaFuncSetAttribute(fused_kernel, cudaFuncAttributeMaxDynamicSharedMemorySize, DYN_BYTES);

    init_kernel<<<1, 1>>>();
    fused_kernel<<<148, 512, DYN_BYTES>>>(xyz, feat, W1, b1, W2, b2, lg, lb, oxyz, ofeat);
}

// round 10
// speedup vs baseline: 1.2802x; 1.0801x over previous
#include <cuda_runtime.h>
#include <cuda_bf16.h>
#include <cstdint>

#define BATCH 4
#define NPTS 8192
#define NSAMP 2048
#define KNN_K 16
#define INDIM 64
#define OUTDIM 128
#define CIN 67

typedef unsigned long long ull;

// ---------------- global coordination state ----------------
__device__ int g_knn[BATCH * NSAMP * KNN_K];
__device__ volatile int g_progress[BATCH];   // FPS samples emitted per batch
__device__ int g_mlpCtr;                     // MLP task counter (1024 tasks)
__device__ volatile int g_knnFlag[128];      // per (chunk,batch) completion

__global__ void init_kernel() {
    g_mlpCtr = 0;
#pragma unroll
    for (int i = 0; i < BATCH; i++) g_progress[i] = 0;
    for (int i = 0; i < 128; i++) g_knnFlag[i] = 0;
}

#define BAR_KNN() asm volatile("bar.sync 2, 256;" ::: "memory")

// ---- packed f32x2 helpers (per-lane bit-identical to scalar ops) ----
__device__ __forceinline__ ull f2pk(float lo, float hi) {
    ull r; asm("mov.b64 %0, {%1,%2};" : "=l"(r) : "f"(lo), "f"(hi)); return r;
}
__device__ __forceinline__ void f2up(ull v, float& lo, float& hi) {
    asm("mov.b64 {%0,%1}, %2;" : "=f"(lo), "=f"(hi) : "l"(v));
}
__device__ __forceinline__ ull f2add(ull a, ull b) {
    ull r; asm("add.rn.f32x2 %0, %1, %2;" : "=l"(r) : "l"(a), "l"(b)); return r;
}
__device__ __forceinline__ ull f2mul(ull a, ull b) {
    ull r; asm("mul.rn.f32x2 %0, %1, %2;" : "=l"(r) : "l"(a), "l"(b)); return r;
}
__device__ __forceinline__ ull f2fma(ull a, ull b, ull c) {
    ull r; asm("fma.rn.f32x2 %0, %1, %2, %3;" : "=l"(r) : "l"(a), "l"(b), "l"(c)); return r;
}

// smem layout (floats):
//   workers: [0,8576) W1s | [8576,24960) W2s | [24960,...) dyn scratch (KNN or MLP)
//   FPS blocks use the whole region for FPS, reload weights afterwards.
#define OFF_W2 8576
#define OFF_DYN 24960
#define MLP_DYN 30720
#define DYN_FLOATS (OFF_DYN + MLP_DYN)     // 55680 floats = 222720 B
#define DYN_BYTES (DYN_FLOATS * 4)

__device__ __forceinline__ int spread3(int v) {
    return (v & 1) | ((v & 2) << 2) | ((v & 4) << 4);
}

// ============================================================================
// FPS: R8 body (1024 threads, 8 pts/thread, f32x2, payload in shared,
// tournament max) + progress publishing every 32 samples.
// ============================================================================
__device__ void fps_part(float* sm, const float* __restrict__ xyz,
                         float* __restrict__ oxyz, int b, int t) {
    float* sxs = sm;
    float* sys = sxs + NPTS;
    float* szs = sys + NPTS;
    int* sorig = (int*)(szs + NPTS);
    int* spay  = sorig + NPTS;
    int* cellCnt = spay + NPTS;             // 512
    int* cellStart = cellCnt + 512;         // 512
    unsigned* pv = (unsigned*)(cellStart + 512);  // 2x32
    unsigned* pp = pv + 64;                       // 2x32
    float* wred = (float*)(pp + 64);        // 32x6 + 6
    int* gpos0 = (int*)(wred + 198);

    const int wid = t >> 5;
    const int lane = t & 31;
    const float* bx = xyz + (size_t)b * NPTS * 3;

    {
        float lx = 3.4e38f, ly = 3.4e38f, lz = 3.4e38f;
        float hx = -3.4e38f, hy = -3.4e38f, hz = -3.4e38f;
        for (int i = t; i < NPTS; i += 1024) {
            float x = bx[3 * i], y = bx[3 * i + 1], z = bx[3 * i + 2];
            lx = fminf(lx, x); hx = fmaxf(hx, x);
            ly = fminf(ly, y); hy = fmaxf(hy, y);
            lz = fminf(lz, z); hz = fmaxf(hz, z);
        }
#pragma unroll
        for (int off = 16; off; off >>= 1) {
            lx = fminf(lx, __shfl_xor_sync(~0u, lx, off));
            ly = fminf(ly, __shfl_xor_sync(~0u, ly, off));
            lz = fminf(lz, __shfl_xor_sync(~0u, lz, off));
            hx = fmaxf(hx, __shfl_xor_sync(~0u, hx, off));
            hy = fmaxf(hy, __shfl_xor_sync(~0u, hy, off));
            hz = fmaxf(hz, __shfl_xor_sync(~0u, hz, off));
        }
        if (lane == 0) {
            wred[wid * 6 + 0] = lx; wred[wid * 6 + 1] = ly; wred[wid * 6 + 2] = lz;
            wred[wid * 6 + 3] = hx; wred[wid * 6 + 4] = hy; wred[wid * 6 + 5] = hz;
        }
        if (t < 512) cellCnt[t] = 0;
    }
    __syncthreads();
    if (t == 0) {
        float lx = wred[0], ly = wred[1], lz = wred[2];
        float hx = wred[3], hy = wred[4], hz = wred[5];
        for (int w = 1; w < 32; w++) {
            lx = fminf(lx, wred[w * 6 + 0]); ly = fminf(ly, wred[w * 6 + 1]);
            lz = fminf(lz, wred[w * 6 + 2]);
            hx = fmaxf(hx, wred[w * 6 + 3]); hy = fmaxf(hy, wred[w * 6 + 4]);
            hz = fmaxf(hz, wred[w * 6 + 5]);
        }
        wred[192] = lx; wred[193] = ly; wred[194] = lz;
        wred[195] = (hx > lx) ? 7.9999f / (hx - lx) : 0.0f;
        wred[196] = (hy > ly) ? 7.9999f / (hy - ly) : 0.0f;
        wred[197] = (hz > lz) ? 7.9999f / (hz - lz) : 0.0f;
    }
    __syncthreads();
    const float lox = wred[192], loy = wred[193], loz = wred[194];
    const float scx = wred[195], scy = wred[196], scz = wred[197];
    for (int i = t; i < NPTS; i += 1024) {
        float x = bx[3 * i], y = bx[3 * i + 1], z = bx[3 * i + 2];
        int qx = (int)((x - lox) * scx); qx = qx < 0 ? 0 : (qx > 7 ? 7 : qx);
        int qy = (int)((y - loy) * scy); qy = qy < 0 ? 0 : (qy > 7 ? 7 : qy);
        int qz = (int)((z - loz) * scz); qz = qz < 0 ? 0 : (qz > 7 ? 7 : qz);
        int ci = (spread3(qx) << 2) | (spread3(qy) << 1) | spread3(qz);
        atomicAdd(&cellCnt[ci], 1);
    }
    __syncthreads();
    if (t < 32) {
        int base = t * 16;
        int loc[16]; int run = 0;
#pragma unroll
        for (int k = 0; k < 16; k++) { loc[k] = run; run += cellCnt[base + k]; }
        int inc = run;
#pragma unroll
        for (int off = 1; off < 32; off <<= 1) {
            int v = __shfl_up_sync(~0u, inc, off);
            if (lane >= off) inc += v;
        }
        int excl = inc - run;
#pragma unroll
        for (int k = 0; k < 16; k++) cellStart[base + k] = excl + loc[k];
    }
    __syncthreads();
    if (t < 512) cellCnt[t] = 0;
    __syncthreads();
    for (int i = t; i < NPTS; i += 1024) {
        float x = bx[3 * i], y = bx[3 * i + 1], z = bx[3 * i + 2];
        int qx = (int)((x - lox) * scx); qx = qx < 0 ? 0 : (qx > 7 ? 7 : qx);
        int qy = (int)((y - loy) * scy); qy = qy < 0 ? 0 : (qy > 7 ? 7 : qy);
        int qz = (int)((z - loz) * scz); qz = qz < 0 ? 0 : (qz > 7 ? 7 : qz);
        int ci = (spread3(qx) << 2) | (spread3(qy) << 1) | spread3(qz);
        int p = cellStart[ci] + atomicAdd(&cellCnt[ci], 1);
        sxs[p] = x; sys[p] = y; szs[p] = z;
        sorig[p] = i;
        spay[p] = (i << 13) | p;
        if (i == 0) *gpos0 = p;
    }
    __syncthreads();

    const int base = t * 8;
    ull px2[4], py2[4], pz2[4];
    float pd[8];
    float blx = 3.4e38f, bly = 3.4e38f, blz = 3.4e38f;
    float bhx = -3.4e38f, bhy = -3.4e38f, bhz = -3.4e38f;
#pragma unroll
    for (int m = 0; m < 4; m++) {
        int p0 = base + 2 * m, p1 = p0 + 1;
        float x0 = sxs[p0], y0 = sys[p0], z0 = szs[p0];
        float x1 = sxs[p1], y1 = sys[p1], z1 = szs[p1];
        px2[m] = f2pk(x0, x1); py2[m] = f2pk(y0, y1); pz2[m] = f2pk(z0, z1);
        pd[2 * m] = 1e10f; pd[2 * m + 1] = 1e10f;
        blx = fminf(blx, fminf(x0, x1)); bhx = fmaxf(bhx, fmaxf(x0, x1));
        bly = fminf(bly, fminf(y0, y1)); bhy = fmaxf(bhy, fmaxf(y0, y1));
        blz = fminf(blz, fminf(z0, z1)); bhz = fmaxf(bhz, fmaxf(z0, z1));
    }
    float hvv = 1e10f;
    int hpp;
    {
        int p = 0x7fffffff;
#pragma unroll
        for (int i = 0; i < 8; i++) p = min(p, spay[base + i]);
        hpp = p;
    }
    __syncthreads();

    float cx, cy, cz;
    {
        int p0 = *gpos0;
        cx = sxs[p0]; cy = sys[p0]; cz = szs[p0];
        if (t == 0) {
            float* o = oxyz + (size_t)b * NSAMP * 3;
            o[0] = cx; o[1] = cy; o[2] = cz;
        }
    }

    int par = 0;
    for (int s = 1; s < NSAMP; s++) {
        const float mcx = -cx, mcy = -cy, mcz = -cz;
        float tx = fmaxf(fmaxf(__fadd_rn(blx, mcx), __fadd_rn(cx, -bhx)), 0.0f);
        float ty = fmaxf(fmaxf(__fadd_rn(bly, mcy), __fadd_rn(cy, -bhy)), 0.0f);
        float tz = fmaxf(fmaxf(__fadd_rn(blz, mcz), __fadd_rn(cz, -bhz)), 0.0f);
        float bnd = __fmul_rn(tx, tx);
        bnd = __fmaf_rn(ty, ty, bnd);
        bnd = __fmaf_rn(tz, tz, bnd);
        bool need = bnd < hvv;
        if (__any_sync(0xffffffffu, need)) {
            const ull ncx = f2pk(mcx, mcx);
            const ull ncy = f2pk(mcy, mcy);
            const ull ncz = f2pk(mcz, mcz);
#pragma unroll
            for (int m = 0; m < 4; m++) {
                ull dx = f2add(px2[m], ncx);
                ull dd = f2mul(dx, dx);
                ull dy = f2add(py2[m], ncy);
                dd = f2fma(dy, dy, dd);
                ull dz = f2add(pz2[m], ncz);
                dd = f2fma(dz, dz, dd);
                float d0, d1;
                f2up(dd, d0, d1);
                pd[2 * m] = fminf(pd[2 * m], d0);
                pd[2 * m + 1] = fminf(pd[2 * m + 1], d1);
            }
            float mv = pd[0];
#pragma unroll
            for (int i = 1; i < 8; i++) mv = fmaxf(mv, pd[i]);
            int p = 0x7fffffff;
#pragma unroll
            for (int i = 0; i < 8; i++)
                p = min(p, (pd[i] == mv) ? spay[base + i] : 0x7fffffff);
            hvv = mv; hpp = p;
        }
        unsigned bmaxv = __float_as_uint(hvv);
        unsigned wv = __reduce_max_sync(0xffffffffu, bmaxv);
        unsigned wp = __reduce_min_sync(0xffffffffu,
                                        (bmaxv == wv) ? (unsigned)hpp : 0x7fffffffu);
        if (lane == 0) { pv[par * 32 + wid] = wv; pp[par * 32 + wid] = wp; }
        __syncthreads();
        unsigned v3 = pv[par * 32 + lane];
        unsigned p3 = pp[par * 32 + lane];
        unsigned gv = __reduce_max_sync(0xffffffffu, v3);
        unsigned gp = __reduce_min_sync(0xffffffffu, (v3 == gv) ? p3 : 0x7fffffffu);
        int pos = (int)(gp & 0x1fffu);
        cx = sxs[pos]; cy = sys[pos]; cz = szs[pos];
        if (t == 0) {
            float* o = oxyz + ((size_t)b * NSAMP + s) * 3;
            o[0] = cx; o[1] = cy; o[2] = cz;
            if ((s & 31) == 31) {
                __threadfence();
                g_progress[b] = s + 1;
            }
        }
        par ^= 1;
    }
    if (t == 0) { __threadfence(); g_progress[b] = NSAMP; }
}

// ============================================================================
// KNN chunk: 64 queries, threads 0-255 active (4/query). Named barrier 2.
// ============================================================================
#define KTS 1024

__device__ void knn_chunk(float* dyn, const float* __restrict__ xyz,
                          const float* __restrict__ qxyz, int b, int q0, int t) {
    if (t >= 256) return;
    float* stx = dyn;
    float* sty = dyn + 1024;
    float* stz = dyn + 2048;
    float* st2 = dyn + 3072;
    float* smd = dyn + 4096;               // 64*48
    int*   smi = (int*)(dyn + 7168);       // 64*48

    const int ql = t >> 2;
    const int par = t & 3;
    const int q = q0 + ql;

    const float* qp = qxyz + ((size_t)b * NSAMP + q) * 3;
    const float qx = qp[0], qy = qp[1], qz = qp[2];
    const float q2 = qx * qx + qy * qy + qz * qz;

    float dk[16];
    int ik[16];
#pragma unroll
    for (int i = 0; i < 16; i++) { dk[i] = 3.4e38f; ik[i] = 0; }

    const float* bx = xyz + (size_t)b * NPTS * 3;
    for (int tile = 0; tile < NPTS / KTS; tile++) {
        BAR_KNN();
        for (int i = t; i < KTS; i += 256) {
            int p = tile * KTS + i;
            float x = bx[p * 3 + 0], y = bx[p * 3 + 1], z = bx[p * 3 + 2];
            stx[i] = x; sty[i] = y; stz[i] = z;
            st2[i] = x * x + y * y + z * z;
        }
        BAR_KNN();
        for (int j = par; j < KTS; j += 4) {
            float dot = qx * stx[j] + qy * sty[j] + qz * stz[j];
            float d = q2 + st2[j] - 2.0f * dot;
            if (d < dk[0]) {
                int idx = tile * KTS + j;
                dk[0] = d; ik[0] = idx;
#pragma unroll
                for (int r = 0; r < 15; r++) {
                    if (dk[r] < dk[r + 1]) {
                        float td = dk[r]; dk[r] = dk[r + 1]; dk[r + 1] = td;
                        int ti = ik[r]; ik[r] = ik[r + 1]; ik[r + 1] = ti;
                    }
                }
            }
        }
    }
    BAR_KNN();

    if (par) {
        int basee = ql * 48 + (par - 1) * 16;
#pragma unroll
        for (int i = 0; i < 16; i++) { smd[basee + i] = dk[i]; smi[basee + i] = ik[i]; }
    }
    BAR_KNN();

    if (par == 0) {
        for (int e = 0; e < 48; e++) {
            float d = smd[ql * 48 + e];
            int idx = smi[ql * 48 + e];
            if (d < dk[0] || (d == dk[0] && idx < ik[0])) {
                dk[0] = d; ik[0] = idx;
#pragma unroll
                for (int r = 0; r < 15; r++) {
                    bool sw = (dk[r] < dk[r + 1]) ||
                              (dk[r] == dk[r + 1] && ik[r] < ik[r + 1]);
                    if (sw) {
                        float td = dk[r]; dk[r] = dk[r + 1]; dk[r + 1] = td;
                        int ti = ik[r]; ik[r] = ik[r + 1]; ik[r + 1] = ti;
                    }
                }
            }
        }
        int* dst = g_knn + (((size_t)b * NSAMP + q) << 4);
#pragma unroll
        for (int i = 0; i < 16; i++) dst[i] = ik[i];
    }
    BAR_KNN();
}

// ============================================================================
// MLP tile: 8 queries (128 rows), ALL 1024 threads, 4x4 register tile.
// Same k-ordering as before -> bit-identical outputs.
// ============================================================================
__device__ void mlp_tile(float* sm, const float* __restrict__ xyz,
                         const float* __restrict__ feat,
                         const float* __restrict__ newxyz,
                         const float* __restrict__ b1, const float* __restrict__ b2,
                         const float* __restrict__ lg, const float* __restrict__ lb,
                         float* __restrict__ outf, int b, int q0, int t) {
    float* W1s = sm;
    float* W2s = sm + OFF_W2;
    float* dyn = sm + OFF_DYN;
    float* Gs  = dyn;               // 128 x 68
    float* Hs  = dyn + 8704;        // 128 x 132
    float* Ps  = dyn + 25600;       // 32 x 128
    float* Qs  = dyn + 29696;       // 8 x 128

    // gather: 8 threads per row
    {
        int r = t >> 3, sub = t & 7;
        int qlq = r >> 4, kk = r & 15;
        int q = q0 + qlq;
        int nidx = g_knn[(((size_t)b * NSAMP + q) << 4) + kk];
        const float* frow = feat + ((size_t)b * NPTS + nidx) * INDIM + sub * 8;
        float* grow = Gs + r * 68;
        float4 v0 = *(const float4*)(frow);
        float4 v1 = *(const float4*)(frow + 4);
        *(float4*)(grow + sub * 8) = v0;
        *(float4*)(grow + sub * 8 + 4) = v1;
        if (sub == 0) {
            const float* prow = xyz + ((size_t)b * NPTS + nidx) * 3;
            const float* crow = newxyz + ((size_t)b * NSAMP + q) * 3;
            grow[64] = prow[0] - crow[0];
            grow[65] = prow[1] - crow[1];
            grow[66] = prow[2] - crow[2];
        }
    }
    __syncthreads();

    const int tx = t & 31, ty = t >> 5;
    const int c0 = tx * 4, r0 = ty * 4;

    float acc[4][4];
    {
        float4 bb = *(const float4*)(b1 + c0);
#pragma unroll
        for (int i = 0; i < 4; i++) {
            acc[i][0] = bb.x; acc[i][1] = bb.y; acc[i][2] = bb.z; acc[i][3] = bb.w;
        }
    }
    for (int k = 0; k < CIN; k++) {
        float4 w = *(const float4*)(W1s + k * 128 + c0);
        float g0 = Gs[(r0 + 0) * 68 + k];
        float g1 = Gs[(r0 + 1) * 68 + k];
        float g2 = Gs[(r0 + 2) * 68 + k];
        float g3 = Gs[(r0 + 3) * 68 + k];
        acc[0][0] += g0 * w.x; acc[0][1] += g0 * w.y; acc[0][2] += g0 * w.z; acc[0][3] += g0 * w.w;
        acc[1][0] += g1 * w.x; acc[1][1] += g1 * w.y; acc[1][2] += g1 * w.z; acc[1][3] += g1 * w.w;
        acc[2][0] += g2 * w.x; acc[2][1] += g2 * w.y; acc[2][2] += g2 * w.z; acc[2][3] += g2 * w.w;
        acc[3][0] += g3 * w.x; acc[3][1] += g3 * w.y; acc[3][2] += g3 * w.z; acc[3][3] += g3 * w.w;
    }
#pragma unroll
    for (int i = 0; i < 4; i++) {
        float4 v;
        v.x = fmaxf(acc[i][0], 0.f); v.y = fmaxf(acc[i][1], 0.f);
        v.z = fmaxf(acc[i][2], 0.f); v.w = fmaxf(acc[i][3], 0.f);
        *(float4*)(Hs + (r0 + i) * 132 + c0) = v;
    }
    __syncthreads();

    {
        float4 bb = *(const float4*)(b2 + c0);
#pragma unroll
        for (int i = 0; i < 4; i++) {
            acc[i][0] = bb.x; acc[i][1] = bb.y; acc[i][2] = bb.z; acc[i][3] = bb.w;
        }
    }
    for (int k = 0; k < OUTDIM; k++) {
        float4 w = *(const float4*)(W2s + k * 128 + c0);
        float h0 = Hs[(r0 + 0) * 132 + k];
        float h1 = Hs[(r0 + 1) * 132 + k];
        float h2 = Hs[(r0 + 2) * 132 + k];
        float h3 = Hs[(r0 + 3) * 132 + k];
        acc[0][0] += h0 * w.x; acc[0][1] += h0 * w.y; acc[0][2] += h0 * w.z; acc[0][3] += h0 * w.w;
        acc[1][0] += h1 * w.x; acc[1][1] += h1 * w.y; acc[1][2] += h1 * w.z; acc[1][3] += h1 * w.w;
        acc[2][0] += h2 * w.x; acc[2][1] += h2 * w.y; acc[2][2] += h2 * w.z; acc[2][3] += h2 * w.w;
        acc[3][0] += h3 * w.x; acc[3][1] += h3 * w.y; acc[3][2] += h3 * w.z; acc[3][3] += h3 * w.w;
    }
    {
        float4 v;
        v.x = fmaxf(fmaxf(acc[0][0], acc[1][0]), fmaxf(acc[2][0], acc[3][0]));
        v.y = fmaxf(fmaxf(acc[0][1], acc[1][1]), fmaxf(acc[2][1], acc[3][1]));
        v.z = fmaxf(fmaxf(acc[0][2], acc[1][2]), fmaxf(acc[2][2], acc[3][2]));
        v.w = fmaxf(fmaxf(acc[0][3], acc[1][3]), fmaxf(acc[2][3], acc[3][3]));
        *(float4*)(Ps + ty * 128 + c0) = v;
    }
    __syncthreads();
    {
        int q = t >> 7, c = t & 127;
        float v = fmaxf(fmaxf(Ps[(4 * q + 0) * 128 + c], Ps[(4 * q + 1) * 128 + c]),
                        fmaxf(Ps[(4 * q + 2) * 128 + c], Ps[(4 * q + 3) * 128 + c]));
        Qs[t] = v;
    }
    __syncthreads();

    if (t < 256) {
        int w = t >> 5, l = t & 31;
        float4 v = *(const float4*)(Qs + w * 128 + l * 4);
        float sum = v.x + v.y + v.z + v.w;
        float sq = fmaf(v.x, v.x, fmaf(v.y, v.y, fmaf(v.z, v.z, v.w * v.w)));
#pragma unroll
        for (int off = 16; off; off >>= 1) {
            sum += __shfl_xor_sync(0xffffffffu, sum, off);
            sq += __shfl_xor_sync(0xffffffffu, sq, off);
        }
        float mu = sum * (1.0f / 128.0f);
        float var = sq * (1.0f / 128.0f) - mu * mu;
        float rs = rsqrtf(var + 1e-5f);
        int qg = q0 + w;
        int c = l * 4;
        float4 o;
        o.x = (v.x - mu) * rs * __ldg(lg + c + 0) + __ldg(lb + c + 0);
        o.y = (v.y - mu) * rs * __ldg(lg + c + 1) + __ldg(lb + c + 1);
        o.z = (v.z - mu) * rs * __ldg(lg + c + 2) + __ldg(lb + c + 2);
        o.w = (v.w - mu) * rs * __ldg(lg + c + 3) + __ldg(lb + c + 3);
        *(float4*)(outf + (((size_t)b * NSAMP + qg) << 7) + c) = o;
    }
    __syncthreads();
}

__device__ void load_weights(float* sm, const float* __restrict__ W1,
                             const float* __restrict__ W2, int t) {
    // W1 permuted: src row sr<3 (xyz) -> 64+sr, else sr-3 (matches G layout)
    for (int e = t; e < CIN * OUTDIM; e += 1024) {
        int sr = e >> 7, c = e & 127;
        int dr = (sr < 3) ? (64 + sr) : (sr - 3);
        sm[dr * 128 + c] = W1[e];
    }
    const float4* src = (const float4*)W2;
    float4* dst = (float4*)(sm + OFF_W2);
    for (int e = t; e < 4096; e += 1024) dst[e] = src[e];
}

// ============================================================================
// Fused persistent kernel: grid 148 x 1024 threads (all co-resident).
// Blocks 0-3: FPS then join MLP pool. Blocks 4-147: workers; first 128 own
// one KNN chunk each (non-blocking readiness check), drain MLP pool otherwise.
// Deadlock-free: a worker blocks on another's KNN flag only when it has no
// pending chunk of its own.
// ============================================================================
__global__ __launch_bounds__(1024, 1)
void fused_kernel(const float* __restrict__ xyz, const float* __restrict__ feat,
                  const float* __restrict__ W1, const float* __restrict__ b1,
                  const float* __restrict__ W2, const float* __restrict__ b2,
                  const float* __restrict__ lg, const float* __restrict__ lb,
                  float* __restrict__ oxyz, float* __restrict__ ofeat) {
    extern __shared__ float sm[];
    __shared__ int shA, shT;
    const int t = threadIdx.x;
    const int bid = blockIdx.x;

    int pendChunk = -1, pendB = 0, pendNeed = 0, pendFlag = -1;

    if (bid < BATCH) {
        fps_part(sm, xyz, oxyz, bid, t);
        __syncthreads();
        load_weights(sm, W1, W2, t);
        __syncthreads();
    } else {
        int w = bid - BATCH;             // 0..143
        if (w < 128) {
            pendChunk = w >> 2;          // 0..31
            pendB = w & 3;
            pendNeed = (pendChunk + 1) * 64;
            pendFlag = w;
        }
        load_weights(sm, W1, W2, t);
        __syncthreads();
    }

    while (true) {
        __syncthreads();
        if (t == 0) {
            int a = 0, task = -1;
            if (pendChunk >= 0 && g_progress[pendB] >= pendNeed) {
                a = 1;                                    // own KNN ready
            } else {
                task = atomicAdd(&g_mlpCtr, 1);
                if (task < 1024) {
                    int fi = (((task >> 2) >> 3) << 2) | (task & 3);
                    int fs = g_knnFlag[fi];
                    a = (!fs && pendChunk >= 0) ? 4 : 2;  // 4: own knn first, then mlp
                } else {
                    a = (pendChunk >= 0) ? 3 : 0;         // 3: must finish own knn
                }
            }
            shA = a; shT = task;
        }
        __syncthreads();
        int a = shA, task = shT;
        if (a == 0) break;

        if (a == 1 || a == 3 || a == 4) {
            if ((a == 3 || a == 4) && t == 0) {
                while (g_progress[pendB] < pendNeed) __nanosleep(64);
            }
            __syncthreads();
            knn_chunk(sm + OFF_DYN, xyz, oxyz, pendB, pendChunk * 64, t);
            __syncthreads();
            if (t == 0) { __threadfence(); g_knnFlag[pendFlag] = 1; }
            pendChunk = -1; pendFlag = -1;
        }
        if (a == 2 || a == 4) {
            int qc = task >> 2, b = task & 3;
            int fi = ((qc >> 3) << 2) | b;
            if (t == 0) {
                while (g_knnFlag[fi] == 0) __nanosleep(64);
            }
            __syncthreads();
            mlp_tile(sm, xyz, feat, oxyz, b1, b2, lg, lb, ofeat, b, qc * 8, t);
        }
    }
}

// ============================================================================
extern "C" void kernel_launch(void* const* d_in, const int* in_sizes, int n_in,
                              void* d_out, int out_size) {
    const float* xyz  = (const float*)d_in[0];
    const float* feat = (const float*)d_in[1];
    const float* W1   = (const float*)d_in[2];
    const float* b1   = (const float*)d_in[3];
    const float* W2   = (const float*)d_in[4];
    const float* b2   = (const float*)d_in[5];
    const float* lg   = (const float*)d_in[6];
    const float* lb   = (const float*)d_in[7];

    float* out = (float*)d_out;
    float* oxyz = out;                                  // (B, S, 3)
    float* ofeat = out + (size_t)BATCH * NSAMP * 3;     // (B, S, 128)

    cudaFuncSetAttribute(fused_kernel, cudaFuncAttributeMaxDynamicSharedMemorySize, DYN_BYTES);

    init_kernel<<<1, 1>>>();
    fused_kernel<<<148, 1024, DYN_BYTES>>>(xyz, feat, W1, b1, W2, b2, lg, lb, oxyz, ofeat);
}